// round 14
// baseline (speedup 1.0000x reference)
#include <cuda_runtime.h>
#include <cuda_fp16.h>
#include <cstdint>

#define BB 4
#define NN 4096
#define DD 512
#define HH 8
#define DHD 64
#define MM 256
#define LLm 16
#define NITER 6
#define KC 33
#define BH (BB*HH)
#define SN2 128
#define NCH2 (NN/SN2)

// ---------------- scratch -------------------------------------------------------
__device__ __align__(16) __half h_xn   [BB*NN*DD];
__device__ __align__(16) __half h_wqkvT[3*DD*DD];
__device__ __align__(16) __half h_woutT[DD*DD];
__device__ __align__(16) __half h_q  [BH*NN*DHD];
__device__ __align__(16) __half h_k  [BH*NN*DHD];
__device__ __align__(16) __half h_v  [BH*NN*DHD];
__device__ __align__(16) __half h_o  [BH*NN*DHD];
__device__ __align__(16) __half h_ql [BH*MM*DHD];
__device__ __align__(16) __half h_kl [BH*MM*DHD];
__device__ __align__(16) __half h_a2 [BH*MM*MM];
__device__ __align__(16) __half h_z  [BH*MM*MM];
__device__ __align__(16) __half h_zT [BH*MM*MM];
__device__ __align__(16) __half h_z2 [BH*MM*MM];
__device__ __align__(16) __half h_z2T[BH*MM*MM];
__device__ __align__(16) __half h_xz [BH*MM*MM];
__device__ __align__(16) __half h_t1T[BH*MM*MM];
__device__ __align__(16) __half h_t2T[BH*MM*MM];
__device__ __align__(16) __half h_a3vT[BH*DHD*MM];    // [d][m]
__device__ __align__(16) __half h_WT [BH*DHD*MM];     // [d][m]
__device__ __align__(16) __half h_att[BB*NN*DD];
__device__ float g_colmax;

// ---------------- helpers ------------------------------------------------------
__device__ __forceinline__ uint32_t h2pack(float a, float b) {
    __half2 h = __floats2half2_rn(a, b);
    return *reinterpret_cast<uint32_t*>(&h);
}
__device__ __forceinline__ uint32_t prmtb(uint32_t a, uint32_t b, uint32_t sel) {
    uint32_t d;
    asm("prmt.b32 %0, %1, %2, %3;" : "=r"(d) : "r"(a), "r"(b), "r"(sel));
    return d;
}
__device__ __forceinline__ void mma_f16(float* c, const uint32_t* a, const uint32_t* b) {
    asm volatile(
        "mma.sync.aligned.m16n8k16.row.col.f32.f16.f16.f32 "
        "{%0,%1,%2,%3}, {%4,%5,%6,%7}, {%8,%9}, {%0,%1,%2,%3};"
        : "+f"(c[0]), "+f"(c[1]), "+f"(c[2]), "+f"(c[3])
        : "r"(a[0]), "r"(a[1]), "r"(a[2]), "r"(a[3]), "r"(b[0]), "r"(b[1]));
}
__device__ __forceinline__ void ldsm4(uint32_t* r, uint32_t saddr) {
    asm volatile("ldmatrix.sync.aligned.m8n8.x4.shared.b16 {%0,%1,%2,%3}, [%4];"
        : "=r"(r[0]), "=r"(r[1]), "=r"(r[2]), "=r"(r[3]) : "r"(saddr));
}
__device__ __forceinline__ void ldsm2(uint32_t* r, uint32_t saddr) {
    asm volatile("ldmatrix.sync.aligned.m8n8.x2.shared.b16 {%0,%1}, [%2];"
        : "=r"(r[0]), "=r"(r[1]) : "r"(saddr));
}
__device__ __forceinline__ void cpa16(uint32_t dst, const void* src) {
    asm volatile("cp.async.cg.shared.global [%0], [%1], 16;" :: "r"(dst), "l"(src));
}
#define CP_COMMIT() asm volatile("cp.async.commit_group;")

// =============================================================================
// gemm_h: C = alpha * A @ B^T, A [M][K] half, B [N][K] half (both k-contig).
// BM=128, BN template, BK=32. 3-stage cp.async + LDSM, one barrier per k-iter.
// 8 warps 4m x 2n.
// MODE 0: p0 = float* C ; MODE 1: qkv split ; MODE 2: y = acc + x + bout
// MODE 3: p0 Cn(half normal), p1 CtRaw(half transp), p2 CtDiag(half transp, dgI-acc)
// =============================================================================
template<int BN, int MODE>
__global__ __launch_bounds__(256, 2) void gemm_h(
    const __half* __restrict__ Ag, const __half* __restrict__ Bg,
    void* __restrict__ p0, void* __restrict__ p1, void* __restrict__ p2,
    int Md, int Nd, int Kd, long sA, long sB, long sC,
    float alpha, float dg)
{
    constexpr int NT = BN / 16;
    constexpr int WN = BN / 2;
    constexpr int NBJ = BN / 64;
    constexpr int BSZ = BN * 16;       // B stage size (u32)

    __shared__ uint32_t As[3][128 * 16];
    __shared__ uint32_t Bs[3][BSZ];

    const __half* A = Ag + (long)blockIdx.z * sA;
    const __half* Bp = Bg + (long)blockIdx.z * sB;
    const int m0 = blockIdx.y * 128;
    const int n0 = blockIdx.x * BN;
    const int tid = threadIdx.x;
    const int wid = tid >> 5, lane = tid & 31;
    const int warpm = wid & 3, warpn = wid >> 2;
    const int lg = lane >> 2, lt = lane & 3;

    const uint32_t asmb = (uint32_t)__cvta_generic_to_shared(&As[0][0]);
    const uint32_t bsmb = (uint32_t)__cvta_generic_to_shared(&Bs[0][0]);

    const int t4  = lane >> 3;
    const int agh = t4 >> 1;
    int aoff[2], asw[2];
#pragma unroll
    for (int mt = 0; mt < 2; mt++) {
        int rr = warpm * 32 + mt * 16 + (t4 & 1) * 8 + (lane & 7);
        aoff[mt] = rr * 64;
        asw[mt]  = (rr >> 1) & 3;
    }
    const int btb = t4 & 1;
    int boff[NT], bsw[NT];
#pragma unroll
    for (int nt = 0; nt < NT; nt++) {
        int n = warpn * WN + nt * 8 + (lane & 7);
        boff[nt] = n * 64;
        bsw[nt]  = (n >> 1) & 3;
    }

    float acc[2][NT][4];
#pragma unroll
    for (int mt = 0; mt < 2; mt++)
#pragma unroll
        for (int nt = 0; nt < NT; nt++)
#pragma unroll
            for (int i = 0; i < 4; i++) acc[mt][nt][i] = 0.f;

    const int nk = Kd >> 5;

#define LOADT(kt, st) do {                                                      \
    const int k0_ = (kt) << 5;                                                  \
    _Pragma("unroll")                                                           \
    for (int j = 0; j < 2; j++) {                                               \
        int e = tid + j * 256;                                                  \
        int row = e >> 2, g = e & 3;                                            \
        uint32_t d = asmb + (uint32_t)(((st) * 2048 + row * 16 +                \
                     4 * (g ^ ((row >> 1) & 3))) << 2);                         \
        cpa16(d, A + (long)(m0 + row) * Kd + k0_ + 8 * g);                      \
    }                                                                           \
    _Pragma("unroll")                                                           \
    for (int j = 0; j < NBJ; j++) {                                             \
        int e = tid + j * 256;                                                  \
        int n = e >> 2, g = e & 3;                                              \
        uint32_t d = bsmb + (uint32_t)(((st) * BSZ + n * 16 +                   \
                     4 * (g ^ ((n >> 1) & 3))) << 2);                           \
        cpa16(d, Bp + (long)(n0 + n) * Kd + k0_ + 8 * g);                       \
    }                                                                           \
    CP_COMMIT();                                                                \
} while (0)

    LOADT(0, 0);
    LOADT(1, 1);

    for (int kt = 0; kt < nk; kt++) {
        const int st = kt % 3;
        if (kt + 1 < nk) asm volatile("cp.async.wait_group 1;");
        else             asm volatile("cp.async.wait_group 0;");
        __syncthreads();

        const uint32_t a_base = asmb + (uint32_t)((st * 2048) << 2);
        const uint32_t b_base = bsmb + (uint32_t)((st * BSZ) << 2);
#pragma unroll
        for (int s = 0; s < 2; s++) {
            uint32_t af[2][4], bf[NT][2];
#pragma unroll
            for (int mt = 0; mt < 2; mt++)
                ldsm4(af[mt], a_base + (uint32_t)((aoff[mt] +
                      ((((s << 1) | agh) ^ asw[mt]) << 4))));
#pragma unroll
            for (int nt = 0; nt < NT; nt++)
                ldsm2(bf[nt], b_base + (uint32_t)((boff[nt] +
                      ((((s << 1) | btb) ^ bsw[nt]) << 4))));
#pragma unroll
            for (int mt = 0; mt < 2; mt++)
#pragma unroll
                for (int nt = 0; nt < NT; nt++)
                    mma_f16(acc[mt][nt], af[mt], bf[nt]);
        }
        if (kt + 2 < nk) LOADT(kt + 2, (kt + 2) % 3);
    }
#undef LOADT

    if (MODE == 0) {
        float* C = (float*)p0 + (long)blockIdx.z * sC;
#pragma unroll
        for (int mt = 0; mt < 2; mt++)
#pragma unroll
            for (int nt = 0; nt < NT; nt++) {
                int r = m0 + warpm * 32 + mt * 16 + lg;
                int c = n0 + warpn * WN + nt * 8 + 2 * lt;
                *(float2*)(C + (long)r * Nd + c) =
                    make_float2(acc[mt][nt][0] * alpha, acc[mt][nt][1] * alpha);
                *(float2*)(C + (long)(r + 8) * Nd + c) =
                    make_float2(acc[mt][nt][2] * alpha, acc[mt][nt][3] * alpha);
            }
    } else if (MODE == 1) {
        __half* qh = (__half*)p0; __half* kh = (__half*)p1; __half* vh = (__half*)p2;
#pragma unroll
        for (int mt = 0; mt < 2; mt++)
#pragma unroll
            for (int nt = 0; nt < NT; nt++) {
                int c = n0 + warpn * WN + nt * 8 + 2 * lt;
                int which = c >> 9, cc = c & 511;
                int h = cc >> 6, d = cc & 63;
                float sc = (which == 0) ? 0.125f : 1.f;
                __half* dsth = (which == 0) ? qh : (which == 1) ? kh : vh;
#pragma unroll
                for (int half_ = 0; half_ < 2; half_++) {
                    int m = m0 + warpm * 32 + mt * 16 + half_ * 8 + lg;
                    int b = m >> 12, n = m & 4095;
                    long dst = ((long)(b * HH + h) * NN + n) * DHD + d;
                    *(uint32_t*)(dsth + dst) = h2pack(acc[mt][nt][half_ * 2] * sc,
                                                      acc[mt][nt][half_ * 2 + 1] * sc);
                }
            }
    } else if (MODE == 2) {
        float* y = (float*)p0;
        const float* xp = (const float*)p1;
        const float* bp = (const float*)p2;
#pragma unroll
        for (int mt = 0; mt < 2; mt++)
#pragma unroll
            for (int nt = 0; nt < NT; nt++) {
                int r = m0 + warpm * 32 + mt * 16 + lg;
                int c = n0 + warpn * WN + nt * 8 + 2 * lt;
                float b0 = bp[c], b1 = bp[c + 1];
                float2 x0 = *(const float2*)(xp + (long)r * Nd + c);
                float2 x1 = *(const float2*)(xp + (long)(r + 8) * Nd + c);
                *(float2*)(y + (long)r * Nd + c) =
                    make_float2(acc[mt][nt][0] + x0.x + b0, acc[mt][nt][1] + x0.y + b1);
                *(float2*)(y + (long)(r + 8) * Nd + c) =
                    make_float2(acc[mt][nt][2] + x1.x + b0, acc[mt][nt][3] + x1.y + b1);
            }
    } else {
        __half* Cn = p0 ? (__half*)p0 + (long)blockIdx.z * sC : nullptr;
        __half* Ctr = p1 ? (__half*)p1 + (long)blockIdx.z * sC : nullptr;
        __half* Ctd = p2 ? (__half*)p2 + (long)blockIdx.z * sC : nullptr;
#pragma unroll
        for (int mt = 0; mt < 2; mt++)
#pragma unroll
            for (int nt = 0; nt < NT; nt++) {
                int r = m0 + warpm * 32 + mt * 16 + lg;
                int c = n0 + warpn * WN + nt * 8 + 2 * lt;
                float v00 = acc[mt][nt][0] * alpha;
                float v01 = acc[mt][nt][1] * alpha;
                float v10 = acc[mt][nt][2] * alpha;
                float v11 = acc[mt][nt][3] * alpha;
                if (Cn) {
                    *(uint32_t*)(Cn + (long)r * Nd + c)       = h2pack(v00, v01);
                    *(uint32_t*)(Cn + (long)(r + 8) * Nd + c) = h2pack(v10, v11);
                }
                if (Ctr) {
                    Ctr[(long)c * Md + r]           = __float2half(v00);
                    Ctr[(long)(c + 1) * Md + r]     = __float2half(v01);
                    Ctr[(long)c * Md + r + 8]       = __float2half(v10);
                    Ctr[(long)(c + 1) * Md + r + 8] = __float2half(v11);
                }
                if (Ctd) {
                    Ctd[(long)c * Md + r]           = __float2half(((r == c)         ? dg : 0.f) - v00);
                    Ctd[(long)(c + 1) * Md + r]     = __float2half(((r == c + 1)     ? dg : 0.f) - v01);
                    Ctd[(long)c * Md + r + 8]       = __float2half(((r + 8 == c)     ? dg : 0.f) - v10);
                    Ctd[(long)(c + 1) * Md + r + 8] = __float2half(((r + 8 == c + 1) ? dg : 0.f) - v11);
                }
            }
    }
}

// =============================================================================
// sim_softmax_h: Out(half) = softmax_row(A @ B^T)  (used for a2 only)
// =============================================================================
__global__ __launch_bounds__(256, 2) void sim_softmax_h(
    const __half* __restrict__ Ag, const __half* __restrict__ Bg,
    __half* __restrict__ Og, long sA, long sB, long sO)
{
    __shared__ uint32_t As[64 * 16];
    __shared__ uint32_t Bs[256 * 16];
    __shared__ float redm[64 * 4];
    __shared__ float reds[64 * 4];

    const __half* A = Ag + (long)blockIdx.z * sA;
    const __half* B = Bg + (long)blockIdx.z * sB;
    __half*       O = Og + (long)blockIdx.z * sO;
    const int m0 = blockIdx.x * 64;
    const int tid = threadIdx.x;
    const int wid = tid >> 5, lane = tid & 31;
    const int warpm = wid & 1, warpn = wid >> 1;
    const int lg = lane >> 2, lt = lane & 3;

    const uint32_t asmb = (uint32_t)__cvta_generic_to_shared(&As[0]);
    const uint32_t bsmb = (uint32_t)__cvta_generic_to_shared(&Bs[0]);

    const int t4  = lane >> 3;
    const int agh = t4 >> 1;
    int aoff[2], asw[2];
#pragma unroll
    for (int mt = 0; mt < 2; mt++) {
        int rr = warpm * 32 + mt * 16 + (t4 & 1) * 8 + (lane & 7);
        aoff[mt] = rr * 64;
        asw[mt]  = (rr >> 1) & 3;
    }
    const int btb = t4 & 1;
    int boff[8], bsw[8];
#pragma unroll
    for (int nt = 0; nt < 8; nt++) {
        int n = warpn * 64 + nt * 8 + (lane & 7);
        boff[nt] = n * 64;
        bsw[nt]  = (n >> 1) & 3;
    }

    float acc[2][8][4];
#pragma unroll
    for (int mt = 0; mt < 2; mt++)
#pragma unroll
        for (int nt = 0; nt < 8; nt++)
#pragma unroll
            for (int i = 0; i < 4; i++) acc[mt][nt][i] = 0.f;

#pragma unroll
    for (int kt = 0; kt < 2; kt++) {
        const int k0 = kt * 32;
        {
            int row = tid >> 2, g = tid & 3;
            uint4 va = *(const uint4*)(A + (long)(m0 + row) * DHD + k0 + 8 * g);
            *(uint4*)&As[row * 16 + 4 * (g ^ ((row >> 1) & 3))] = va;
        }
#pragma unroll
        for (int j = 0; j < 4; j++) {
            int e = tid + j * 256;
            int n = e >> 2, g = e & 3;
            uint4 vb = *(const uint4*)(B + (long)n * DHD + k0 + 8 * g);
            *(uint4*)&Bs[n * 16 + 4 * (g ^ ((n >> 1) & 3))] = vb;
        }
        __syncthreads();

#pragma unroll
        for (int s = 0; s < 2; s++) {
            uint32_t af[2][4], bf[8][2];
#pragma unroll
            for (int mt = 0; mt < 2; mt++)
                ldsm4(af[mt], asmb + (uint32_t)(aoff[mt] +
                      ((((s << 1) | agh) ^ asw[mt]) << 4)));
#pragma unroll
            for (int nt = 0; nt < 8; nt++)
                ldsm2(bf[nt], bsmb + (uint32_t)(boff[nt] +
                      ((((s << 1) | btb) ^ bsw[nt]) << 4)));
#pragma unroll
            for (int mt = 0; mt < 2; mt++)
#pragma unroll
                for (int nt = 0; nt < 8; nt++)
                    mma_f16(acc[mt][nt], af[mt], bf[nt]);
        }
        __syncthreads();
    }

#pragma unroll
    for (int mt = 0; mt < 2; mt++)
#pragma unroll
        for (int half_ = 0; half_ < 2; half_++) {
            float mx = -1e30f;
#pragma unroll
            for (int nt = 0; nt < 8; nt++) {
                mx = fmaxf(mx, acc[mt][nt][half_ * 2]);
                mx = fmaxf(mx, acc[mt][nt][half_ * 2 + 1]);
            }
            mx = fmaxf(mx, __shfl_xor_sync(~0u, mx, 1));
            mx = fmaxf(mx, __shfl_xor_sync(~0u, mx, 2));
            int rloc = warpm * 32 + mt * 16 + half_ * 8 + lg;
            if (lt == 0) redm[rloc * 4 + warpn] = mx;
        }
    __syncthreads();
#pragma unroll
    for (int mt = 0; mt < 2; mt++)
#pragma unroll
        for (int half_ = 0; half_ < 2; half_++) {
            int rloc = warpm * 32 + mt * 16 + half_ * 8 + lg;
            float m4 = fmaxf(fmaxf(redm[rloc * 4 + 0], redm[rloc * 4 + 1]),
                             fmaxf(redm[rloc * 4 + 2], redm[rloc * 4 + 3]));
            float s = 0.f;
#pragma unroll
            for (int nt = 0; nt < 8; nt++) {
                float e0 = __expf(acc[mt][nt][half_ * 2]     - m4);
                float e1 = __expf(acc[mt][nt][half_ * 2 + 1] - m4);
                acc[mt][nt][half_ * 2]     = e0;
                acc[mt][nt][half_ * 2 + 1] = e1;
                s += e0 + e1;
            }
            s += __shfl_xor_sync(~0u, s, 1);
            s += __shfl_xor_sync(~0u, s, 2);
            if (lt == 0) reds[rloc * 4 + warpn] = s;
        }
    __syncthreads();
#pragma unroll
    for (int mt = 0; mt < 2; mt++)
#pragma unroll
        for (int half_ = 0; half_ < 2; half_++) {
            int rloc = warpm * 32 + mt * 16 + half_ * 8 + lg;
            float tot = reds[rloc * 4 + 0] + reds[rloc * 4 + 1]
                      + reds[rloc * 4 + 2] + reds[rloc * 4 + 3];
            float inv = 1.f / tot;
            int r = m0 + rloc;
#pragma unroll
            for (int nt = 0; nt < 8; nt++) {
                int c = warpn * 64 + nt * 8 + 2 * lt;
                *(uint32_t*)(O + (long)r * MM + c) =
                    h2pack(acc[mt][nt][half_ * 2] * inv, acc[mt][nt][half_ * 2 + 1] * inv);
            }
        }
}

// =============================================================================
// sim_out_h: o = softmax_row(q @ kl^T) @ W, fully fused (a1 never materialized).
// =============================================================================
__global__ __launch_bounds__(256, 2) void sim_out_h()
{
    __shared__ uint32_t S[8192];
    __shared__ float redm[64 * 4];
    __shared__ float reds[64 * 4];

    const int bh = blockIdx.z;
    const __half* A = h_q  + (long)bh * NN * DHD;
    const __half* B = h_kl + (long)bh * MM * DHD;
    const __half* WTb = h_WT + (long)bh * DHD * MM;
    const int m0 = blockIdx.x * 64;
    const int tid = threadIdx.x;
    const int wid = tid >> 5, lane = tid & 31;
    const int warpm = wid & 1, warpn = wid >> 1;
    const int lg = lane >> 2, lt = lane & 3;

    uint32_t* As = S;
    uint32_t* Bs = S + 1024;
    const uint32_t asmb = (uint32_t)__cvta_generic_to_shared(As);
    const uint32_t bsmb = (uint32_t)__cvta_generic_to_shared(Bs);

    const int t4  = lane >> 3;
    const int agh = t4 >> 1;
    int aoff[2], asw[2];
#pragma unroll
    for (int mt = 0; mt < 2; mt++) {
        int rr = warpm * 32 + mt * 16 + (t4 & 1) * 8 + (lane & 7);
        aoff[mt] = rr * 64;
        asw[mt]  = (rr >> 1) & 3;
    }
    const int btb = t4 & 1;
    int boff[8], bsw[8];
#pragma unroll
    for (int nt = 0; nt < 8; nt++) {
        int n = warpn * 64 + nt * 8 + (lane & 7);
        boff[nt] = n * 64;
        bsw[nt]  = (n >> 1) & 3;
    }

    float acc[2][8][4];
#pragma unroll
    for (int mt = 0; mt < 2; mt++)
#pragma unroll
        for (int nt = 0; nt < 8; nt++)
#pragma unroll
            for (int i = 0; i < 4; i++) acc[mt][nt][i] = 0.f;

#pragma unroll
    for (int kt = 0; kt < 2; kt++) {
        const int k0 = kt * 32;
        {
            int row = tid >> 2, g = tid & 3;
            uint4 va = *(const uint4*)(A + (long)(m0 + row) * DHD + k0 + 8 * g);
            *(uint4*)&As[row * 16 + 4 * (g ^ ((row >> 1) & 3))] = va;
        }
#pragma unroll
        for (int j = 0; j < 4; j++) {
            int e = tid + j * 256;
            int n = e >> 2, g = e & 3;
            uint4 vb = *(const uint4*)(B + (long)n * DHD + k0 + 8 * g);
            *(uint4*)&Bs[n * 16 + 4 * (g ^ ((n >> 1) & 3))] = vb;
        }
        __syncthreads();

#pragma unroll
        for (int s = 0; s < 2; s++) {
            uint32_t af[2][4], bf[8][2];
#pragma unroll
            for (int mt = 0; mt < 2; mt++)
                ldsm4(af[mt], asmb + (uint32_t)(aoff[mt] +
                      ((((s << 1) | agh) ^ asw[mt]) << 4)));
#pragma unroll
            for (int nt = 0; nt < 8; nt++)
                ldsm2(bf[nt], bsmb + (uint32_t)(boff[nt] +
                      ((((s << 1) | btb) ^ bsw[nt]) << 4)));
#pragma unroll
            for (int mt = 0; mt < 2; mt++)
#pragma unroll
                for (int nt = 0; nt < 8; nt++)
                    mma_f16(acc[mt][nt], af[mt], bf[nt]);
        }
        __syncthreads();
    }

#pragma unroll
    for (int mt = 0; mt < 2; mt++)
#pragma unroll
        for (int half_ = 0; half_ < 2; half_++) {
            float mx = -1e30f;
#pragma unroll
            for (int nt = 0; nt < 8; nt++) {
                mx = fmaxf(mx, acc[mt][nt][half_ * 2]);
                mx = fmaxf(mx, acc[mt][nt][half_ * 2 + 1]);
            }
            mx = fmaxf(mx, __shfl_xor_sync(~0u, mx, 1));
            mx = fmaxf(mx, __shfl_xor_sync(~0u, mx, 2));
            int rloc = warpm * 32 + mt * 16 + half_ * 8 + lg;
            if (lt == 0) redm[rloc * 4 + warpn] = mx;
        }
    __syncthreads();
#pragma unroll
    for (int mt = 0; mt < 2; mt++)
#pragma unroll
        for (int half_ = 0; half_ < 2; half_++) {
            int rloc = warpm * 32 + mt * 16 + half_ * 8 + lg;
            float m4 = fmaxf(fmaxf(redm[rloc * 4 + 0], redm[rloc * 4 + 1]),
                             fmaxf(redm[rloc * 4 + 2], redm[rloc * 4 + 3]));
            float s = 0.f;
#pragma unroll
            for (int nt = 0; nt < 8; nt++) {
                float e0 = __expf(acc[mt][nt][half_ * 2]     - m4);
                float e1 = __expf(acc[mt][nt][half_ * 2 + 1] - m4);
                acc[mt][nt][half_ * 2]     = e0;
                acc[mt][nt][half_ * 2 + 1] = e1;
                s += e0 + e1;
            }
            s += __shfl_xor_sync(~0u, s, 1);
            s += __shfl_xor_sync(~0u, s, 2);
            if (lt == 0) reds[rloc * 4 + warpn] = s;
        }
    __syncthreads();
#pragma unroll
    for (int mt = 0; mt < 2; mt++)
#pragma unroll
        for (int half_ = 0; half_ < 2; half_++) {
            int rloc = warpm * 32 + mt * 16 + half_ * 8 + lg;
            float tot = reds[rloc * 4 + 0] + reds[rloc * 4 + 1]
                      + reds[rloc * 4 + 2] + reds[rloc * 4 + 3];
            float inv = 1.f / tot;
#pragma unroll
            for (int nt = 0; nt < 8; nt++) {
                int kp = warpn * 32 + nt * 4 + lt;
                S[rloc * 128 + (kp ^ ((rloc & 7) << 2))] =
                    h2pack(acc[mt][nt][half_ * 2] * inv, acc[mt][nt][half_ * 2 + 1] * inv);
            }
        }
    __syncthreads();

    float oacc[2][2][4];
#pragma unroll
    for (int mt = 0; mt < 2; mt++)
#pragma unroll
        for (int nt = 0; nt < 2; nt++)
#pragma unroll
            for (int i = 0; i < 4; i++) oacc[mt][nt][i] = 0.f;

#pragma unroll
    for (int s = 0; s < 16; s++) {
        const int kp0 = s * 8;
        uint32_t af[2][4], bf[2][2];
#pragma unroll
        for (int mt = 0; mt < 2; mt++) {
            int mr = warpm * 32 + mt * 16 + lg;
            af[mt][0] = S[mr * 128 + ((kp0 + lt) ^ ((mr & 7) << 2))];
            af[mt][1] = S[(mr + 8) * 128 + ((kp0 + lt) ^ (((mr + 8) & 7) << 2))];
            af[mt][2] = S[mr * 128 + ((kp0 + lt + 4) ^ ((mr & 7) << 2))];
            af[mt][3] = S[(mr + 8) * 128 + ((kp0 + lt + 4) ^ (((mr + 8) & 7) << 2))];
        }
#pragma unroll
        for (int nt = 0; nt < 2; nt++) {
            int d = warpn * 16 + nt * 8 + lg;
            bf[nt][0] = *(const uint32_t*)(WTb + (long)d * MM + s * 16 + 2 * lt);
            bf[nt][1] = *(const uint32_t*)(WTb + (long)d * MM + s * 16 + 8 + 2 * lt);
        }
#pragma unroll
        for (int mt = 0; mt < 2; mt++)
#pragma unroll
            for (int nt = 0; nt < 2; nt++)
                mma_f16(oacc[mt][nt], af[mt], bf[nt]);
    }

    __half* ob = h_o + (long)bh * NN * DHD;
#pragma unroll
    for (int mt = 0; mt < 2; mt++)
#pragma unroll
        for (int half_ = 0; half_ < 2; half_++) {
            int r = m0 + warpm * 32 + mt * 16 + half_ * 8 + lg;
#pragma unroll
            for (int nt = 0; nt < 2; nt++) {
                int d = warpn * 16 + nt * 8 + 2 * lt;
                *(uint32_t*)(ob + (long)r * DHD + d) =
                    h2pack(oacc[mt][nt][half_ * 2], oacc[mt][nt][half_ * 2 + 1]);
            }
        }
}

// =============================================================================
// a3v_flash_h: a3vT = (softmax_row(ql @ k^T) @ v)^T, SN2=128 chunks.
// =============================================================================
__global__ __launch_bounds__(256, 2) void a3v_flash_h()
{
    __shared__ uint32_t Ks[128 * 32];
    __shared__ uint32_t Vs[64 * 64];
    __shared__ uint32_t Ps[32 * 64];
    __shared__ float redm[32 * 4];
    __shared__ float reds[32 * 4];

    const int bh = blockIdx.z;
    const int m0 = blockIdx.x * 32;
    const __half* ql = h_ql + (long)bh * MM * DHD;
    const __half* kg = h_k  + (long)bh * NN * DHD;
    const __half* vg = h_v  + (long)bh * NN * DHD;

    const int tid = threadIdx.x;
    const int wid = tid >> 5, lane = tid & 31;
    const int warpm = wid & 1, warpn = wid >> 1;
    const int lg = lane >> 2, lt = lane & 3;

    uint32_t aq[4][4];
    {
        int mr = m0 + warpm * 16;
#pragma unroll
        for (int s = 0; s < 4; s++) {
            int d0 = s * 16 + 2 * lt;
            aq[s][0] = *(const uint32_t*)(ql + (long)(mr + lg) * DHD + d0);
            aq[s][1] = *(const uint32_t*)(ql + (long)(mr + 8 + lg) * DHD + d0);
            aq[s][2] = *(const uint32_t*)(ql + (long)(mr + lg) * DHD + d0 + 8);
            aq[s][3] = *(const uint32_t*)(ql + (long)(mr + 8 + lg) * DHD + d0 + 8);
        }
    }

    float oacc[2][4];
#pragma unroll
    for (int nt = 0; nt < 2; nt++)
#pragma unroll
        for (int i = 0; i < 4; i++) oacc[nt][i] = 0.f;
    float mprev[2] = {-1e30f, -1e30f};
    float lsum[2]  = {0.f, 0.f};

    uint4 kpre[4];
    uint2 vpa[4], vpb[4];
#pragma unroll
    for (int j = 0; j < 4; j++) {
        int e = tid + j * 256;
        { int tok = e >> 3, g = e & 7;
          kpre[j] = *(const uint4*)(kg + (long)tok * DHD + 8 * g); }
        { int kpt = e >> 4, d4 = (e & 15) << 2;
          vpa[j] = *(const uint2*)(vg + (long)(2 * kpt) * DHD + d4);
          vpb[j] = *(const uint2*)(vg + (long)(2 * kpt + 1) * DHD + d4); }
    }

    for (int ch = 0; ch < NCH2; ch++) {
        __syncthreads();
#pragma unroll
        for (int j = 0; j < 4; j++) {
            int e = tid + j * 256;
            { int tok = e >> 3, g = e & 7;
              *(uint4*)&Ks[tok * 32 + 4 * (g ^ (tok & 7))] = kpre[j]; }
            { int kpt = e >> 4, d4 = (e & 15) << 2;
              uint4 w;
              w.x = prmtb(vpa[j].x, vpb[j].x, 0x5410);
              w.y = prmtb(vpa[j].x, vpb[j].x, 0x7632);
              w.z = prmtb(vpa[j].y, vpb[j].y, 0x5410);
              w.w = prmtb(vpa[j].y, vpb[j].y, 0x7632);
              *(uint4*)&Vs[kpt * 64 + (d4 ^ ((kpt & 3) << 3))] = w; }
        }
        if (ch + 1 < NCH2) {
            const __half* kc = kg + (long)(ch + 1) * SN2 * DHD;
            const __half* vc = vg + (long)(ch + 1) * SN2 * DHD;
#pragma unroll
            for (int j = 0; j < 4; j++) {
                int e = tid + j * 256;
                { int tok = e >> 3, g = e & 7;
                  kpre[j] = *(const uint4*)(kc + (long)tok * DHD + 8 * g); }
                { int kpt = e >> 4, d4 = (e & 15) << 2;
                  vpa[j] = *(const uint2*)(vc + (long)(2 * kpt) * DHD + d4);
                  vpb[j] = *(const uint2*)(vc + (long)(2 * kpt + 1) * DHD + d4); }
            }
        }
        __syncthreads();

        float sacc[4][4];
#pragma unroll
        for (int nt = 0; nt < 4; nt++)
#pragma unroll
            for (int i = 0; i < 4; i++) sacc[nt][i] = 0.f;
#pragma unroll
        for (int s = 0; s < 4; s++) {
            uint32_t bf[4][2];
#pragma unroll
            for (int nt = 0; nt < 4; nt++) {
                int c = warpn * 32 + nt * 8 + lg;
                bf[nt][0] = Ks[c * 32 + lt + 4 * ((2 * s) ^ (c & 7))];
                bf[nt][1] = Ks[c * 32 + lt + 4 * ((2 * s + 1) ^ (c & 7))];
            }
#pragma unroll
            for (int nt = 0; nt < 4; nt++)
                mma_f16(sacc[nt], aq[s], bf[nt]);
        }

#pragma unroll
        for (int half_ = 0; half_ < 2; half_++) {
            float mx = -1e30f;
#pragma unroll
            for (int nt = 0; nt < 4; nt++) {
                mx = fmaxf(mx, sacc[nt][half_ * 2]);
                mx = fmaxf(mx, sacc[nt][half_ * 2 + 1]);
            }
            mx = fmaxf(mx, __shfl_xor_sync(~0u, mx, 1));
            mx = fmaxf(mx, __shfl_xor_sync(~0u, mx, 2));
            if (lt == 0) redm[(warpm * 16 + half_ * 8 + lg) * 4 + warpn] = mx;
        }
        __syncthreads();

        float scale[2];
#pragma unroll
        for (int half_ = 0; half_ < 2; half_++) {
            int row = warpm * 16 + half_ * 8 + lg;
            float mch = fmaxf(fmaxf(redm[row * 4 + 0], redm[row * 4 + 1]),
                              fmaxf(redm[row * 4 + 2], redm[row * 4 + 3]));
            float mnew = fmaxf(mprev[half_], mch);
            scale[half_] = __expf(mprev[half_] - mnew);
            mprev[half_] = mnew;
            float s = 0.f;
#pragma unroll
            for (int nt = 0; nt < 4; nt++) {
                float e0 = __expf(sacc[nt][half_ * 2]     - mnew);
                float e1 = __expf(sacc[nt][half_ * 2 + 1] - mnew);
                sacc[nt][half_ * 2]     = e0;
                sacc[nt][half_ * 2 + 1] = e1;
                s += e0 + e1;
            }
            s += __shfl_xor_sync(~0u, s, 1);
            s += __shfl_xor_sync(~0u, s, 2);
            if (lt == 0) reds[row * 4 + warpn] = s;
#pragma unroll
            for (int nt = 0; nt < 4; nt++) {
                int kp = warpn * 16 + nt * 4 + lt;
                Ps[row * 64 + (kp ^ ((row & 7) << 2))] =
                    h2pack(sacc[nt][half_ * 2], sacc[nt][half_ * 2 + 1]);
            }
        }
        __syncthreads();

#pragma unroll
        for (int half_ = 0; half_ < 2; half_++) {
            int row = warpm * 16 + half_ * 8 + lg;
            lsum[half_] = lsum[half_] * scale[half_]
                        + reds[row * 4 + 0] + reds[row * 4 + 1]
                        + reds[row * 4 + 2] + reds[row * 4 + 3];
        }
#pragma unroll
        for (int nt = 0; nt < 2; nt++) {
            oacc[nt][0] *= scale[0]; oacc[nt][1] *= scale[0];
            oacc[nt][2] *= scale[1]; oacc[nt][3] *= scale[1];
        }

#pragma unroll
        for (int s = 0; s < 8; s++) {
            const int kp0 = s * 8;
            int mr = warpm * 16 + lg;
            uint32_t af[4];
            af[0] = Ps[mr * 64 + ((kp0 + lt) ^ ((mr & 7) << 2))];
            af[1] = Ps[(mr + 8) * 64 + ((kp0 + lt) ^ (((mr + 8) & 7) << 2))];
            af[2] = Ps[mr * 64 + ((kp0 + lt + 4) ^ ((mr & 7) << 2))];
            af[3] = Ps[(mr + 8) * 64 + ((kp0 + lt + 4) ^ (((mr + 8) & 7) << 2))];
            uint32_t bf[2][2];
#pragma unroll
            for (int nt = 0; nt < 2; nt++) {
                int d = warpn * 16 + nt * 8 + lg;
                bf[nt][0] = Vs[(kp0 + lt) * 64 + (d ^ (lt << 3))];
                bf[nt][1] = Vs[(kp0 + lt + 4) * 64 + (d ^ (lt << 3))];
            }
#pragma unroll
            for (int nt = 0; nt < 2; nt++)
                mma_f16(oacc[nt], af, bf[nt]);
        }
    }

    __half* outb = h_a3vT + (long)bh * DHD * MM;
#pragma unroll
    for (int half_ = 0; half_ < 2; half_++) {
        float inv = 1.f / lsum[half_];
        int r = m0 + warpm * 16 + half_ * 8 + lg;
#pragma unroll
        for (int nt = 0; nt < 2; nt++) {
            int d = warpn * 16 + nt * 8 + 2 * lt;
            outb[(long)d * MM + r]       = __float2half(oacc[nt][half_ * 2] * inv);
            outb[(long)(d + 1) * MM + r] = __float2half(oacc[nt][half_ * 2 + 1] * inv);
        }
    }
}

// ---------------- LayerNorm (half out) -----------------------------------------
__global__ __launch_bounds__(256) void ln_kernel(
    const float* __restrict__ x, const float* __restrict__ w, const float* __restrict__ b)
{
    long row = blockIdx.x;
    const float* xr = x + row * DD;
    int t = threadIdx.x;
    float v0 = xr[t], v1 = xr[t + 256];
    __shared__ float red[32];

    float s = v0 + v1;
    for (int o = 16; o > 0; o >>= 1) s += __shfl_xor_sync(~0u, s, o);
    if ((t & 31) == 0) red[t >> 5] = s;
    __syncthreads();
    if (t < 32) {
        float ss = (t < 8) ? red[t] : 0.f;
        for (int o = 4; o > 0; o >>= 1) ss += __shfl_xor_sync(~0u, ss, o);
        if (t == 0) red[0] = ss;
    }
    __syncthreads();
    float mu = red[0] * (1.f / DD);
    __syncthreads();

    float d0 = v0 - mu, d1 = v1 - mu;
    float q = d0 * d0 + d1 * d1;
    for (int o = 16; o > 0; o >>= 1) q += __shfl_xor_sync(~0u, q, o);
    if ((t & 31) == 0) red[t >> 5] = q;
    __syncthreads();
    if (t < 32) {
        float ss = (t < 8) ? red[t] : 0.f;
        for (int o = 4; o > 0; o >>= 1) ss += __shfl_xor_sync(~0u, ss, o);
        if (t == 0) red[0] = ss;
    }
    __syncthreads();
    float inv = rsqrtf(red[0] * (1.f / DD) + 1e-5f);
    h_xn[row * DD + t]       = __float2half(d0 * inv * w[t]       + b[t]);
    h_xn[row * DD + t + 256] = __float2half(d1 * inv * w[t + 256] + b[t + 256]);
}

// ---------------- weight conversion --------------------------------------------
__global__ void conv_weights(const float* __restrict__ wq, const float* __restrict__ wo)
{
    int i = blockIdx.x * 256 + threadIdx.x;
    {
        int n = i / DD, k2 = i % DD;
        h_wqkvT[i] = __float2half(wq[(long)k2 * (3 * DD) + n]);
    }
    if (i < DD * DD) {
        int n = i / DD, k2 = i % DD;
        h_woutT[i] = __float2half(wo[(long)k2 * DD + n]);
    }
}

// ---------------- landmarks (one half2 per thread, 1024 blocks) ----------------
__global__ void landmarks()
{
    long i = (long)blockIdx.x * 256 + threadIdx.x;    // BH*MM*32 d-pairs
    int dp = i & 31; long r = i >> 5;
    int m = r % MM;  int bh = r / MM;
    long base = ((long)bh * NN + m * LLm) * DHD + dp * 2;
    float sq0 = 0.f, sq1 = 0.f, sk0 = 0.f, sk1 = 0.f;
#pragma unroll
    for (int u = 0; u < LLm; u++) {
        float2 fq = __half22float2(*(const __half2*)(h_q + base + u * DHD));
        float2 fk = __half22float2(*(const __half2*)(h_k + base + u * DHD));
        sq0 += fq.x; sq1 += fq.y;
        sk0 += fk.x; sk1 += fk.y;
    }
    long out = ((long)bh * MM + m) * DHD + dp * 2;
    *(uint32_t*)(h_ql + out) = h2pack(sq0 * (1.f / LLm), sq1 * (1.f / LLm));
    *(uint32_t*)(h_kl + out) = h2pack(sk0 * (1.f / LLm), sk1 * (1.f / LLm));
}

// ---------------- pinv init ----------------------------------------------------
__global__ void init_colmax() { g_colmax = 0.f; }

__global__ __launch_bounds__(256) void colmax_kernel()
{
    int bh = blockIdx.x, j = threadIdx.x;
    const __half* a = h_a2 + (long)bh * MM * MM;
    float s = 0.f;
    for (int i = 0; i < MM; i++) s += __half2float(a[i * MM + j]);
    __shared__ float red[32];
    float m = s;
    for (int o = 16; o > 0; o >>= 1) m = fmaxf(m, __shfl_xor_sync(~0u, m, o));
    if ((j & 31) == 0) red[j >> 5] = m;
    __syncthreads();
    if (j < 32) {
        float m2 = (j < 8) ? red[j] : -1e30f;
        for (int o = 4; o > 0; o >>= 1) m2 = fmaxf(m2, __shfl_xor_sync(~0u, m2, o));
        if (j == 0) atomicMax((int*)&g_colmax, __float_as_int(m2));
    }
}

__global__ void zinit()
{
    long i = (long)blockIdx.x * 256 + threadIdx.x;
    int col = i % MM; long r = i / MM;
    int row = r % MM; int bh = r / MM;
    float inv = 1.f / g_colmax;
    h_zT[i] = __float2half(__half2float(h_a2[i]) * inv);
    h_z [i] = __float2half(__half2float(h_a2[((long)bh * MM + col) * MM + row]) * inv);
}

// ---------------- fused reshape + depthwise conv (all half) --------------------
__global__ void att_conv(const float* __restrict__ rw)
{
    long i = (long)blockIdx.x * 256 + threadIdx.x;
    int dq = i % 16; long r = i / 16;
    int h = r % HH;  long r2 = r / HH;
    int n = r2 % NN; int b = r2 / NN;
    long bhbase = (long)(b * HH + h) * NN;
    const __half* vb = h_v + bhbase * DHD;
    uint2 ov = *(const uint2*)(h_o + (bhbase + n) * DHD + dq * 4);
    float2 o0 = __half22float2(*(const __half2*)&ov.x);
    float2 o1 = __half22float2(*(const __half2*)&ov.y);
    float a0 = o0.x, a1 = o0.y, a2 = o1.x, a3 = o1.y;
#pragma unroll
    for (int j = 0; j < KC; j++) {
        int tt = n + j - KC / 2;
        if (tt >= 0 && tt < NN) {
            float w = rw[h * KC + j];
            uint2 vv = *(const uint2*)(vb + (long)tt * DHD + dq * 4);
            float2 v0 = __half22float2(*(const __half2*)&vv.x);
            float2 v1 = __half22float2(*(const __half2*)&vv.y);
            a0 += w * v0.x; a1 += w * v0.y; a2 += w * v1.x; a3 += w * v1.y;
        }
    }
    uint2 w2;
    w2.x = h2pack(a0, a1);
    w2.y = h2pack(a2, a3);
    *(uint2*)&h_att[((long)(b * NN + n)) * DD + h * DHD + dq * 4] = w2;
}

// ---------------- host orchestration -------------------------------------------
extern "C" void kernel_launch(void* const* d_in, const int* in_sizes, int n_in,
                              void* d_out, int out_size)
{
    const float* x      = (const float*)d_in[0];
    const float* norm_w = (const float*)d_in[1];
    const float* norm_b = (const float*)d_in[2];
    const float* w_qkv  = (const float*)d_in[3];
    const float* w_out  = (const float*)d_in[4];
    const float* b_out  = (const float*)d_in[5];
    const float* res_w  = (const float*)d_in[6];
    float* y = (float*)d_out;

    __half *p_xn, *p_wqkvT, *p_woutT, *p_q, *p_k, *p_v, *p_ql, *p_kl;
    __half *p_a2, *p_z, *p_zT, *p_z2, *p_z2T, *p_xz, *p_t1T, *p_t2T, *p_a3vT, *p_WT, *p_att;
    cudaGetSymbolAddress((void**)&p_xn,   h_xn);
    cudaGetSymbolAddress((void**)&p_wqkvT,h_wqkvT);
    cudaGetSymbolAddress((void**)&p_woutT,h_woutT);
    cudaGetSymbolAddress((void**)&p_q,    h_q);
    cudaGetSymbolAddress((void**)&p_k,    h_k);
    cudaGetSymbolAddress((void**)&p_v,    h_v);
    cudaGetSymbolAddress((void**)&p_ql,   h_ql);
    cudaGetSymbolAddress((void**)&p_kl,   h_kl);
    cudaGetSymbolAddress((void**)&p_a2,   h_a2);
    cudaGetSymbolAddress((void**)&p_z,    h_z);
    cudaGetSymbolAddress((void**)&p_zT,   h_zT);
    cudaGetSymbolAddress((void**)&p_z2,   h_z2);
    cudaGetSymbolAddress((void**)&p_z2T,  h_z2T);
    cudaGetSymbolAddress((void**)&p_xz,   h_xz);
    cudaGetSymbolAddress((void**)&p_t1T,  h_t1T);
    cudaGetSymbolAddress((void**)&p_t2T,  h_t2T);
    cudaGetSymbolAddress((void**)&p_a3vT, h_a3vT);
    cudaGetSymbolAddress((void**)&p_WT,   h_WT);
    cudaGetSymbolAddress((void**)&p_att,  h_att);

    const long MM2 = (long)MM * MM;
    void* nul = nullptr;

    // 1. LayerNorm + weight conversion
    ln_kernel<<<BB * NN, 256>>>(x, norm_w, norm_b);
    conv_weights<<<(3 * DD * DD) / 256, 256>>>(w_qkv, w_out);
    // 2. qkv GEMM with fused split
    gemm_h<128, 1><<<dim3((3 * DD) / 128, (BB * NN) / 128, 1), 256>>>(
        p_xn, p_wqkvT, p_q, p_k, p_v,
        BB * NN, 3 * DD, DD, 0, 0, 0, 1.f, 0.f);
    // 3. landmarks
    landmarks<<<(BH * MM * 32) / 256, 256>>>();
    // 4. a2 = softmax(ql @ kl^T)
    sim_softmax_h<<<dim3(MM / 64, 1, BH), 256>>>(
        p_ql, p_kl, p_a2, (long)MM * DHD, (long)MM * DHD, MM2);
    // 5. pinv init
    init_colmax<<<1, 1>>>();
    colmax_kernel<<<BH, 256>>>();
    zinit<<<(int)((long)BH * MM * MM / 256), 256>>>();
    // 6. Newton-Schulz
    __half *zin = p_z, *zinT = p_zT, *zout = p_z2, *zoutT = p_z2T;
    for (int it = 0; it < NITER; it++) {
        gemm_h<64, 3><<<dim3(MM / 64, MM / 128, BH), 256>>>(
            p_a2, zinT, p_xz, nul, p_t1T, MM, MM, MM, MM2, MM2, MM2, 1.f, 7.f);
        gemm_h<64, 3><<<dim3(MM / 64, MM / 128, BH), 256>>>(
            p_xz, p_t1T, nul, nul, p_t2T, MM, MM, MM, MM2, MM2, MM2, 1.f, 15.f);
        gemm_h<64, 3><<<dim3(MM / 64, MM / 128, BH), 256>>>(
            p_xz, p_t2T, nul, nul, p_t1T, MM, MM, MM, MM2, MM2, MM2, 1.f, 13.f);
        gemm_h<64, 3><<<dim3(MM / 64, MM / 128, BH), 256>>>(
            zin, p_t1T, zout, zoutT, nul, MM, MM, MM, MM2, MM2, MM2, 0.25f, 0.f);
        __half* t;
        t = zin;  zin  = zout;  zout  = t;
        t = zinT; zinT = zoutT; zoutT = t;
    }
    // 7. a3vT = (softmax(ql @ k^T) @ v)^T  (flash)
    a3v_flash_h<<<dim3(MM / 32, 1, BH), 256>>>();
    // 8. WT = (z @ a3v)^T
    gemm_h<64, 3><<<dim3(1, MM / 128, BH), 256>>>(
        zin, p_a3vT, nul, p_WT, nul, MM, DHD, MM,
        MM2, (long)DHD * MM, (long)DHD * MM, 1.f, 0.f);
    // 9. o = softmax(q @ kl^T) @ W  (fully fused)
    sim_out_h<<<dim3(NN / 64, 1, BH), 256>>>();
    // 10. att = reshape(o) + conv(v)
    att_conv<<<(BB * NN * HH * 16) / 256, 256>>>(res_w);
    // 11. y = att @ w_out + x + b_out
    gemm_h<128, 2><<<dim3(DD / 128, (BB * NN) / 128, 1), 256>>>(
        p_att, p_woutT, y, (void*)x, (void*)b_out,
        BB * NN, DD, DD, 0, 0, 0, 1.f, 0.f);
}

// round 15
// speedup vs baseline: 1.0141x; 1.0141x over previous
#include <cuda_runtime.h>
#include <cuda_fp16.h>
#include <cstdint>

#define BB 4
#define NN 4096
#define DD 512
#define HH 8
#define DHD 64
#define MM 256
#define LLm 16
#define NITER 6
#define KC 33
#define BH (BB*HH)
#define SN2 128
#define NCH2 (NN/SN2)

// ---------------- scratch -------------------------------------------------------
__device__ __align__(16) __half h_xn   [BB*NN*DD];
__device__ __align__(16) __half h_wqkvT[3*DD*DD];
__device__ __align__(16) __half h_woutT[DD*DD];
__device__ __align__(16) __half h_q  [BH*NN*DHD];
__device__ __align__(16) __half h_k  [BH*NN*DHD];
__device__ __align__(16) __half h_v  [BH*NN*DHD];
__device__ __align__(16) __half h_o  [BH*NN*DHD];
__device__ __align__(16) __half h_ql [BH*MM*DHD];
__device__ __align__(16) __half h_kl [BH*MM*DHD];
__device__ __align__(16) __half h_a2 [BH*MM*MM];
__device__ __align__(16) __half h_z  [BH*MM*MM];
__device__ __align__(16) __half h_zT [BH*MM*MM];
__device__ __align__(16) __half h_z2 [BH*MM*MM];
__device__ __align__(16) __half h_z2T[BH*MM*MM];
__device__ __align__(16) __half h_xz [BH*MM*MM];
__device__ __align__(16) __half h_t1T[BH*MM*MM];
__device__ __align__(16) __half h_t2T[BH*MM*MM];
__device__ __align__(16) __half h_a3vT[BH*DHD*MM];    // [d][m]
__device__ __align__(16) __half h_WT [BH*DHD*MM];     // [d][m]
__device__ __align__(16) __half h_att[BB*NN*DD];
__device__ float g_colmax;

// ---------------- helpers ------------------------------------------------------
__device__ __forceinline__ uint32_t h2pack(float a, float b) {
    __half2 h = __floats2half2_rn(a, b);
    return *reinterpret_cast<uint32_t*>(&h);
}
__device__ __forceinline__ uint32_t prmtb(uint32_t a, uint32_t b, uint32_t sel) {
    uint32_t d;
    asm("prmt.b32 %0, %1, %2, %3;" : "=r"(d) : "r"(a), "r"(b), "r"(sel));
    return d;
}
__device__ __forceinline__ void mma_f16(float* c, const uint32_t* a, const uint32_t* b) {
    asm volatile(
        "mma.sync.aligned.m16n8k16.row.col.f32.f16.f16.f32 "
        "{%0,%1,%2,%3}, {%4,%5,%6,%7}, {%8,%9}, {%0,%1,%2,%3};"
        : "+f"(c[0]), "+f"(c[1]), "+f"(c[2]), "+f"(c[3])
        : "r"(a[0]), "r"(a[1]), "r"(a[2]), "r"(a[3]), "r"(b[0]), "r"(b[1]));
}
__device__ __forceinline__ void ldsm4(uint32_t* r, uint32_t saddr) {
    asm volatile("ldmatrix.sync.aligned.m8n8.x4.shared.b16 {%0,%1,%2,%3}, [%4];"
        : "=r"(r[0]), "=r"(r[1]), "=r"(r[2]), "=r"(r[3]) : "r"(saddr));
}
__device__ __forceinline__ void ldsm2(uint32_t* r, uint32_t saddr) {
    asm volatile("ldmatrix.sync.aligned.m8n8.x2.shared.b16 {%0,%1}, [%2];"
        : "=r"(r[0]), "=r"(r[1]) : "r"(saddr));
}
__device__ __forceinline__ void cpa16(uint32_t dst, const void* src) {
    asm volatile("cp.async.cg.shared.global [%0], [%1], 16;" :: "r"(dst), "l"(src));
}
#define CP_COMMIT() asm volatile("cp.async.commit_group;")

// =============================================================================
// gemm_h: C = alpha * A @ B^T, A [M][K] half, B [N][K] half (both k-contig).
// BM=128, BN template, BK=32. 2-stage cp.async + LDSM (round-13 proven form).
// 8 warps 4m x 2n.
// MODE 0: p0 = float* C ; MODE 1: qkv split ; MODE 2: y = acc + x + bout
// MODE 3: p0 Cn(half normal), p1 CtRaw(half transp), p2 CtDiag(half transp, dgI-acc)
// =============================================================================
template<int BN, int MODE>
__global__ __launch_bounds__(256, 2) void gemm_h(
    const __half* __restrict__ Ag, const __half* __restrict__ Bg,
    void* __restrict__ p0, void* __restrict__ p1, void* __restrict__ p2,
    int Md, int Nd, int Kd, long sA, long sB, long sC,
    float alpha, float dg)
{
    constexpr int NT = BN / 16;
    constexpr int WN = BN / 2;
    constexpr int NBJ = BN / 64;

    __shared__ uint32_t As[2][128 * 16];
    __shared__ uint32_t Bs[2][BN * 16];

    const __half* A = Ag + (long)blockIdx.z * sA;
    const __half* Bp = Bg + (long)blockIdx.z * sB;
    const int m0 = blockIdx.y * 128;
    const int n0 = blockIdx.x * BN;
    const int tid = threadIdx.x;
    const int wid = tid >> 5, lane = tid & 31;
    const int warpm = wid & 3, warpn = wid >> 2;
    const int lg = lane >> 2, lt = lane & 3;

    const uint32_t asmb = (uint32_t)__cvta_generic_to_shared(&As[0][0]);
    const uint32_t bsmb = (uint32_t)__cvta_generic_to_shared(&Bs[0][0]);

    const int t4  = lane >> 3;
    const int agh = t4 >> 1;
    int aoff[2], asw[2];
#pragma unroll
    for (int mt = 0; mt < 2; mt++) {
        int rr = warpm * 32 + mt * 16 + (t4 & 1) * 8 + (lane & 7);
        aoff[mt] = rr * 64;
        asw[mt]  = (rr >> 1) & 3;
    }
    const int btb = t4 & 1;
    int boff[NT], bsw[NT];
#pragma unroll
    for (int nt = 0; nt < NT; nt++) {
        int n = warpn * WN + nt * 8 + (lane & 7);
        boff[nt] = n * 64;
        bsw[nt]  = (n >> 1) & 3;
    }

    float acc[2][NT][4];
#pragma unroll
    for (int mt = 0; mt < 2; mt++)
#pragma unroll
        for (int nt = 0; nt < NT; nt++)
#pragma unroll
            for (int i = 0; i < 4; i++) acc[mt][nt][i] = 0.f;

    const int nk = Kd >> 5;

#define LOADT(kt, st) do {                                                      \
    const int k0_ = (kt) << 5;                                                  \
    _Pragma("unroll")                                                           \
    for (int j = 0; j < 2; j++) {                                               \
        int e = tid + j * 256;                                                  \
        int row = e >> 2, g = e & 3;                                            \
        uint32_t d = asmb + (uint32_t)(((st) * 2048 + row * 16 +                \
                     4 * (g ^ ((row >> 1) & 3))) << 2);                         \
        cpa16(d, A + (long)(m0 + row) * Kd + k0_ + 8 * g);                      \
    }                                                                           \
    _Pragma("unroll")                                                           \
    for (int j = 0; j < NBJ; j++) {                                             \
        int e = tid + j * 256;                                                  \
        int n = e >> 2, g = e & 3;                                              \
        uint32_t d = bsmb + (uint32_t)(((st) * (BN * 16) + n * 16 +             \
                     4 * (g ^ ((n >> 1) & 3))) << 2);                           \
        cpa16(d, Bp + (long)(n0 + n) * Kd + k0_ + 8 * g);                       \
    }                                                                           \
    CP_COMMIT();                                                                \
} while (0)

    LOADT(0, 0);

    for (int kt = 0; kt < nk; kt++) {
        const int st = kt & 1;
        if (kt + 1 < nk) {
            LOADT(kt + 1, st ^ 1);
            asm volatile("cp.async.wait_group 1;");
        } else {
            asm volatile("cp.async.wait_group 0;");
        }
        __syncthreads();

        const uint32_t a_base = asmb + (uint32_t)((st * 2048) << 2);
        const uint32_t b_base = bsmb + (uint32_t)((st * (BN * 16)) << 2);
#pragma unroll
        for (int s = 0; s < 2; s++) {
            uint32_t af[2][4], bf[NT][2];
#pragma unroll
            for (int mt = 0; mt < 2; mt++)
                ldsm4(af[mt], a_base + (uint32_t)((aoff[mt] +
                      ((((s << 1) | agh) ^ asw[mt]) << 4))));
#pragma unroll
            for (int nt = 0; nt < NT; nt++)
                ldsm2(bf[nt], b_base + (uint32_t)((boff[nt] +
                      ((((s << 1) | btb) ^ bsw[nt]) << 4))));
#pragma unroll
            for (int mt = 0; mt < 2; mt++)
#pragma unroll
                for (int nt = 0; nt < NT; nt++)
                    mma_f16(acc[mt][nt], af[mt], bf[nt]);
        }
        __syncthreads();
    }
#undef LOADT

    if (MODE == 0) {
        float* C = (float*)p0 + (long)blockIdx.z * sC;
#pragma unroll
        for (int mt = 0; mt < 2; mt++)
#pragma unroll
            for (int nt = 0; nt < NT; nt++) {
                int r = m0 + warpm * 32 + mt * 16 + lg;
                int c = n0 + warpn * WN + nt * 8 + 2 * lt;
                *(float2*)(C + (long)r * Nd + c) =
                    make_float2(acc[mt][nt][0] * alpha, acc[mt][nt][1] * alpha);
                *(float2*)(C + (long)(r + 8) * Nd + c) =
                    make_float2(acc[mt][nt][2] * alpha, acc[mt][nt][3] * alpha);
            }
    } else if (MODE == 1) {
        __half* qh = (__half*)p0; __half* kh = (__half*)p1; __half* vh = (__half*)p2;
#pragma unroll
        for (int mt = 0; mt < 2; mt++)
#pragma unroll
            for (int nt = 0; nt < NT; nt++) {
                int c = n0 + warpn * WN + nt * 8 + 2 * lt;
                int which = c >> 9, cc = c & 511;
                int h = cc >> 6, d = cc & 63;
                float sc = (which == 0) ? 0.125f : 1.f;
                __half* dsth = (which == 0) ? qh : (which == 1) ? kh : vh;
#pragma unroll
                for (int half_ = 0; half_ < 2; half_++) {
                    int m = m0 + warpm * 32 + mt * 16 + half_ * 8 + lg;
                    int b = m >> 12, n = m & 4095;
                    long dst = ((long)(b * HH + h) * NN + n) * DHD + d;
                    *(uint32_t*)(dsth + dst) = h2pack(acc[mt][nt][half_ * 2] * sc,
                                                      acc[mt][nt][half_ * 2 + 1] * sc);
                }
            }
    } else if (MODE == 2) {
        float* y = (float*)p0;
        const float* xp = (const float*)p1;
        const float* bp = (const float*)p2;
#pragma unroll
        for (int mt = 0; mt < 2; mt++)
#pragma unroll
            for (int nt = 0; nt < NT; nt++) {
                int r = m0 + warpm * 32 + mt * 16 + lg;
                int c = n0 + warpn * WN + nt * 8 + 2 * lt;
                float b0 = bp[c], b1 = bp[c + 1];
                float2 x0 = *(const float2*)(xp + (long)r * Nd + c);
                float2 x1 = *(const float2*)(xp + (long)(r + 8) * Nd + c);
                *(float2*)(y + (long)r * Nd + c) =
                    make_float2(acc[mt][nt][0] + x0.x + b0, acc[mt][nt][1] + x0.y + b1);
                *(float2*)(y + (long)(r + 8) * Nd + c) =
                    make_float2(acc[mt][nt][2] + x1.x + b0, acc[mt][nt][3] + x1.y + b1);
            }
    } else {
        __half* Cn = p0 ? (__half*)p0 + (long)blockIdx.z * sC : nullptr;
        __half* Ctr = p1 ? (__half*)p1 + (long)blockIdx.z * sC : nullptr;
        __half* Ctd = p2 ? (__half*)p2 + (long)blockIdx.z * sC : nullptr;
#pragma unroll
        for (int mt = 0; mt < 2; mt++)
#pragma unroll
            for (int nt = 0; nt < NT; nt++) {
                int r = m0 + warpm * 32 + mt * 16 + lg;
                int c = n0 + warpn * WN + nt * 8 + 2 * lt;
                float v00 = acc[mt][nt][0] * alpha;
                float v01 = acc[mt][nt][1] * alpha;
                float v10 = acc[mt][nt][2] * alpha;
                float v11 = acc[mt][nt][3] * alpha;
                if (Cn) {
                    *(uint32_t*)(Cn + (long)r * Nd + c)       = h2pack(v00, v01);
                    *(uint32_t*)(Cn + (long)(r + 8) * Nd + c) = h2pack(v10, v11);
                }
                if (Ctr) {
                    Ctr[(long)c * Md + r]           = __float2half(v00);
                    Ctr[(long)(c + 1) * Md + r]     = __float2half(v01);
                    Ctr[(long)c * Md + r + 8]       = __float2half(v10);
                    Ctr[(long)(c + 1) * Md + r + 8] = __float2half(v11);
                }
                if (Ctd) {
                    Ctd[(long)c * Md + r]           = __float2half(((r == c)         ? dg : 0.f) - v00);
                    Ctd[(long)(c + 1) * Md + r]     = __float2half(((r == c + 1)     ? dg : 0.f) - v01);
                    Ctd[(long)c * Md + r + 8]       = __float2half(((r + 8 == c)     ? dg : 0.f) - v10);
                    Ctd[(long)(c + 1) * Md + r + 8] = __float2half(((r + 8 == c + 1) ? dg : 0.f) - v11);
                }
            }
    }
}

// =============================================================================
// sim_softmax_h: Out(half) = softmax_row(A @ B^T)  (used for a2 only)
// =============================================================================
__global__ __launch_bounds__(256, 2) void sim_softmax_h(
    const __half* __restrict__ Ag, const __half* __restrict__ Bg,
    __half* __restrict__ Og, long sA, long sB, long sO)
{
    __shared__ uint32_t As[64 * 16];
    __shared__ uint32_t Bs[256 * 16];
    __shared__ float redm[64 * 4];
    __shared__ float reds[64 * 4];

    const __half* A = Ag + (long)blockIdx.z * sA;
    const __half* B = Bg + (long)blockIdx.z * sB;
    __half*       O = Og + (long)blockIdx.z * sO;
    const int m0 = blockIdx.x * 64;
    const int tid = threadIdx.x;
    const int wid = tid >> 5, lane = tid & 31;
    const int warpm = wid & 1, warpn = wid >> 1;
    const int lg = lane >> 2, lt = lane & 3;

    const uint32_t asmb = (uint32_t)__cvta_generic_to_shared(&As[0]);
    const uint32_t bsmb = (uint32_t)__cvta_generic_to_shared(&Bs[0]);

    const int t4  = lane >> 3;
    const int agh = t4 >> 1;
    int aoff[2], asw[2];
#pragma unroll
    for (int mt = 0; mt < 2; mt++) {
        int rr = warpm * 32 + mt * 16 + (t4 & 1) * 8 + (lane & 7);
        aoff[mt] = rr * 64;
        asw[mt]  = (rr >> 1) & 3;
    }
    const int btb = t4 & 1;
    int boff[8], bsw[8];
#pragma unroll
    for (int nt = 0; nt < 8; nt++) {
        int n = warpn * 64 + nt * 8 + (lane & 7);
        boff[nt] = n * 64;
        bsw[nt]  = (n >> 1) & 3;
    }

    float acc[2][8][4];
#pragma unroll
    for (int mt = 0; mt < 2; mt++)
#pragma unroll
        for (int nt = 0; nt < 8; nt++)
#pragma unroll
            for (int i = 0; i < 4; i++) acc[mt][nt][i] = 0.f;

#pragma unroll
    for (int kt = 0; kt < 2; kt++) {
        const int k0 = kt * 32;
        {
            int row = tid >> 2, g = tid & 3;
            uint4 va = *(const uint4*)(A + (long)(m0 + row) * DHD + k0 + 8 * g);
            *(uint4*)&As[row * 16 + 4 * (g ^ ((row >> 1) & 3))] = va;
        }
#pragma unroll
        for (int j = 0; j < 4; j++) {
            int e = tid + j * 256;
            int n = e >> 2, g = e & 3;
            uint4 vb = *(const uint4*)(B + (long)n * DHD + k0 + 8 * g);
            *(uint4*)&Bs[n * 16 + 4 * (g ^ ((n >> 1) & 3))] = vb;
        }
        __syncthreads();

#pragma unroll
        for (int s = 0; s < 2; s++) {
            uint32_t af[2][4], bf[8][2];
#pragma unroll
            for (int mt = 0; mt < 2; mt++)
                ldsm4(af[mt], asmb + (uint32_t)(aoff[mt] +
                      ((((s << 1) | agh) ^ asw[mt]) << 4)));
#pragma unroll
            for (int nt = 0; nt < 8; nt++)
                ldsm2(bf[nt], bsmb + (uint32_t)(boff[nt] +
                      ((((s << 1) | btb) ^ bsw[nt]) << 4)));
#pragma unroll
            for (int mt = 0; mt < 2; mt++)
#pragma unroll
                for (int nt = 0; nt < 8; nt++)
                    mma_f16(acc[mt][nt], af[mt], bf[nt]);
        }
        __syncthreads();
    }

#pragma unroll
    for (int mt = 0; mt < 2; mt++)
#pragma unroll
        for (int half_ = 0; half_ < 2; half_++) {
            float mx = -1e30f;
#pragma unroll
            for (int nt = 0; nt < 8; nt++) {
                mx = fmaxf(mx, acc[mt][nt][half_ * 2]);
                mx = fmaxf(mx, acc[mt][nt][half_ * 2 + 1]);
            }
            mx = fmaxf(mx, __shfl_xor_sync(~0u, mx, 1));
            mx = fmaxf(mx, __shfl_xor_sync(~0u, mx, 2));
            int rloc = warpm * 32 + mt * 16 + half_ * 8 + lg;
            if (lt == 0) redm[rloc * 4 + warpn] = mx;
        }
    __syncthreads();
#pragma unroll
    for (int mt = 0; mt < 2; mt++)
#pragma unroll
        for (int half_ = 0; half_ < 2; half_++) {
            int rloc = warpm * 32 + mt * 16 + half_ * 8 + lg;
            float m4 = fmaxf(fmaxf(redm[rloc * 4 + 0], redm[rloc * 4 + 1]),
                             fmaxf(redm[rloc * 4 + 2], redm[rloc * 4 + 3]));
            float s = 0.f;
#pragma unroll
            for (int nt = 0; nt < 8; nt++) {
                float e0 = __expf(acc[mt][nt][half_ * 2]     - m4);
                float e1 = __expf(acc[mt][nt][half_ * 2 + 1] - m4);
                acc[mt][nt][half_ * 2]     = e0;
                acc[mt][nt][half_ * 2 + 1] = e1;
                s += e0 + e1;
            }
            s += __shfl_xor_sync(~0u, s, 1);
            s += __shfl_xor_sync(~0u, s, 2);
            if (lt == 0) reds[rloc * 4 + warpn] = s;
        }
    __syncthreads();
#pragma unroll
    for (int mt = 0; mt < 2; mt++)
#pragma unroll
        for (int half_ = 0; half_ < 2; half_++) {
            int rloc = warpm * 32 + mt * 16 + half_ * 8 + lg;
            float tot = reds[rloc * 4 + 0] + reds[rloc * 4 + 1]
                      + reds[rloc * 4 + 2] + reds[rloc * 4 + 3];
            float inv = 1.f / tot;
            int r = m0 + rloc;
#pragma unroll
            for (int nt = 0; nt < 8; nt++) {
                int c = warpn * 64 + nt * 8 + 2 * lt;
                *(uint32_t*)(O + (long)r * MM + c) =
                    h2pack(acc[mt][nt][half_ * 2] * inv, acc[mt][nt][half_ * 2 + 1] * inv);
            }
        }
}

// =============================================================================
// sim_out_h: o = softmax_row(q @ kl^T) @ W, fully fused (a1 never materialized).
// =============================================================================
__global__ __launch_bounds__(256, 2) void sim_out_h()
{
    __shared__ uint32_t S[8192];
    __shared__ float redm[64 * 4];
    __shared__ float reds[64 * 4];

    const int bh = blockIdx.z;
    const __half* A = h_q  + (long)bh * NN * DHD;
    const __half* B = h_kl + (long)bh * MM * DHD;
    const __half* WTb = h_WT + (long)bh * DHD * MM;
    const int m0 = blockIdx.x * 64;
    const int tid = threadIdx.x;
    const int wid = tid >> 5, lane = tid & 31;
    const int warpm = wid & 1, warpn = wid >> 1;
    const int lg = lane >> 2, lt = lane & 3;

    uint32_t* As = S;
    uint32_t* Bs = S + 1024;
    const uint32_t asmb = (uint32_t)__cvta_generic_to_shared(As);
    const uint32_t bsmb = (uint32_t)__cvta_generic_to_shared(Bs);

    const int t4  = lane >> 3;
    const int agh = t4 >> 1;
    int aoff[2], asw[2];
#pragma unroll
    for (int mt = 0; mt < 2; mt++) {
        int rr = warpm * 32 + mt * 16 + (t4 & 1) * 8 + (lane & 7);
        aoff[mt] = rr * 64;
        asw[mt]  = (rr >> 1) & 3;
    }
    const int btb = t4 & 1;
    int boff[8], bsw[8];
#pragma unroll
    for (int nt = 0; nt < 8; nt++) {
        int n = warpn * 64 + nt * 8 + (lane & 7);
        boff[nt] = n * 64;
        bsw[nt]  = (n >> 1) & 3;
    }

    float acc[2][8][4];
#pragma unroll
    for (int mt = 0; mt < 2; mt++)
#pragma unroll
        for (int nt = 0; nt < 8; nt++)
#pragma unroll
            for (int i = 0; i < 4; i++) acc[mt][nt][i] = 0.f;

#pragma unroll
    for (int kt = 0; kt < 2; kt++) {
        const int k0 = kt * 32;
        {
            int row = tid >> 2, g = tid & 3;
            uint4 va = *(const uint4*)(A + (long)(m0 + row) * DHD + k0 + 8 * g);
            *(uint4*)&As[row * 16 + 4 * (g ^ ((row >> 1) & 3))] = va;
        }
#pragma unroll
        for (int j = 0; j < 4; j++) {
            int e = tid + j * 256;
            int n = e >> 2, g = e & 3;
            uint4 vb = *(const uint4*)(B + (long)n * DHD + k0 + 8 * g);
            *(uint4*)&Bs[n * 16 + 4 * (g ^ ((n >> 1) & 3))] = vb;
        }
        __syncthreads();

#pragma unroll
        for (int s = 0; s < 2; s++) {
            uint32_t af[2][4], bf[8][2];
#pragma unroll
            for (int mt = 0; mt < 2; mt++)
                ldsm4(af[mt], asmb + (uint32_t)(aoff[mt] +
                      ((((s << 1) | agh) ^ asw[mt]) << 4)));
#pragma unroll
            for (int nt = 0; nt < 8; nt++)
                ldsm2(bf[nt], bsmb + (uint32_t)(boff[nt] +
                      ((((s << 1) | btb) ^ bsw[nt]) << 4)));
#pragma unroll
            for (int mt = 0; mt < 2; mt++)
#pragma unroll
                for (int nt = 0; nt < 8; nt++)
                    mma_f16(acc[mt][nt], af[mt], bf[nt]);
        }
        __syncthreads();
    }

#pragma unroll
    for (int mt = 0; mt < 2; mt++)
#pragma unroll
        for (int half_ = 0; half_ < 2; half_++) {
            float mx = -1e30f;
#pragma unroll
            for (int nt = 0; nt < 8; nt++) {
                mx = fmaxf(mx, acc[mt][nt][half_ * 2]);
                mx = fmaxf(mx, acc[mt][nt][half_ * 2 + 1]);
            }
            mx = fmaxf(mx, __shfl_xor_sync(~0u, mx, 1));
            mx = fmaxf(mx, __shfl_xor_sync(~0u, mx, 2));
            int rloc = warpm * 32 + mt * 16 + half_ * 8 + lg;
            if (lt == 0) redm[rloc * 4 + warpn] = mx;
        }
    __syncthreads();
#pragma unroll
    for (int mt = 0; mt < 2; mt++)
#pragma unroll
        for (int half_ = 0; half_ < 2; half_++) {
            int rloc = warpm * 32 + mt * 16 + half_ * 8 + lg;
            float m4 = fmaxf(fmaxf(redm[rloc * 4 + 0], redm[rloc * 4 + 1]),
                             fmaxf(redm[rloc * 4 + 2], redm[rloc * 4 + 3]));
            float s = 0.f;
#pragma unroll
            for (int nt = 0; nt < 8; nt++) {
                float e0 = __expf(acc[mt][nt][half_ * 2]     - m4);
                float e1 = __expf(acc[mt][nt][half_ * 2 + 1] - m4);
                acc[mt][nt][half_ * 2]     = e0;
                acc[mt][nt][half_ * 2 + 1] = e1;
                s += e0 + e1;
            }
            s += __shfl_xor_sync(~0u, s, 1);
            s += __shfl_xor_sync(~0u, s, 2);
            if (lt == 0) reds[rloc * 4 + warpn] = s;
        }
    __syncthreads();
#pragma unroll
    for (int mt = 0; mt < 2; mt++)
#pragma unroll
        for (int half_ = 0; half_ < 2; half_++) {
            int rloc = warpm * 32 + mt * 16 + half_ * 8 + lg;
            float tot = reds[rloc * 4 + 0] + reds[rloc * 4 + 1]
                      + reds[rloc * 4 + 2] + reds[rloc * 4 + 3];
            float inv = 1.f / tot;
#pragma unroll
            for (int nt = 0; nt < 8; nt++) {
                int kp = warpn * 32 + nt * 4 + lt;
                S[rloc * 128 + (kp ^ ((rloc & 7) << 2))] =
                    h2pack(acc[mt][nt][half_ * 2] * inv, acc[mt][nt][half_ * 2 + 1] * inv);
            }
        }
    __syncthreads();

    float oacc[2][2][4];
#pragma unroll
    for (int mt = 0; mt < 2; mt++)
#pragma unroll
        for (int nt = 0; nt < 2; nt++)
#pragma unroll
            for (int i = 0; i < 4; i++) oacc[mt][nt][i] = 0.f;

#pragma unroll
    for (int s = 0; s < 16; s++) {
        const int kp0 = s * 8;
        uint32_t af[2][4], bf[2][2];
#pragma unroll
        for (int mt = 0; mt < 2; mt++) {
            int mr = warpm * 32 + mt * 16 + lg;
            af[mt][0] = S[mr * 128 + ((kp0 + lt) ^ ((mr & 7) << 2))];
            af[mt][1] = S[(mr + 8) * 128 + ((kp0 + lt) ^ (((mr + 8) & 7) << 2))];
            af[mt][2] = S[mr * 128 + ((kp0 + lt + 4) ^ ((mr & 7) << 2))];
            af[mt][3] = S[(mr + 8) * 128 + ((kp0 + lt + 4) ^ (((mr + 8) & 7) << 2))];
        }
#pragma unroll
        for (int nt = 0; nt < 2; nt++) {
            int d = warpn * 16 + nt * 8 + lg;
            bf[nt][0] = *(const uint32_t*)(WTb + (long)d * MM + s * 16 + 2 * lt);
            bf[nt][1] = *(const uint32_t*)(WTb + (long)d * MM + s * 16 + 8 + 2 * lt);
        }
#pragma unroll
        for (int mt = 0; mt < 2; mt++)
#pragma unroll
            for (int nt = 0; nt < 2; nt++)
                mma_f16(oacc[mt][nt], af[mt], bf[nt]);
    }

    __half* ob = h_o + (long)bh * NN * DHD;
#pragma unroll
    for (int mt = 0; mt < 2; mt++)
#pragma unroll
        for (int half_ = 0; half_ < 2; half_++) {
            int r = m0 + warpm * 32 + mt * 16 + half_ * 8 + lg;
#pragma unroll
            for (int nt = 0; nt < 2; nt++) {
                int d = warpn * 16 + nt * 8 + 2 * lt;
                *(uint32_t*)(ob + (long)r * DHD + d) =
                    h2pack(oacc[mt][nt][half_ * 2], oacc[mt][nt][half_ * 2 + 1]);
            }
        }
}

// =============================================================================
// a3v_flash_h: a3vT = (softmax_row(ql @ k^T) @ v)^T, SN2=128 chunks.
// =============================================================================
__global__ __launch_bounds__(256, 2) void a3v_flash_h()
{
    __shared__ uint32_t Ks[128 * 32];
    __shared__ uint32_t Vs[64 * 64];
    __shared__ uint32_t Ps[32 * 64];
    __shared__ float redm[32 * 4];
    __shared__ float reds[32 * 4];

    const int bh = blockIdx.z;
    const int m0 = blockIdx.x * 32;
    const __half* ql = h_ql + (long)bh * MM * DHD;
    const __half* kg = h_k  + (long)bh * NN * DHD;
    const __half* vg = h_v  + (long)bh * NN * DHD;

    const int tid = threadIdx.x;
    const int wid = tid >> 5, lane = tid & 31;
    const int warpm = wid & 1, warpn = wid >> 1;
    const int lg = lane >> 2, lt = lane & 3;

    uint32_t aq[4][4];
    {
        int mr = m0 + warpm * 16;
#pragma unroll
        for (int s = 0; s < 4; s++) {
            int d0 = s * 16 + 2 * lt;
            aq[s][0] = *(const uint32_t*)(ql + (long)(mr + lg) * DHD + d0);
            aq[s][1] = *(const uint32_t*)(ql + (long)(mr + 8 + lg) * DHD + d0);
            aq[s][2] = *(const uint32_t*)(ql + (long)(mr + lg) * DHD + d0 + 8);
            aq[s][3] = *(const uint32_t*)(ql + (long)(mr + 8 + lg) * DHD + d0 + 8);
        }
    }

    float oacc[2][4];
#pragma unroll
    for (int nt = 0; nt < 2; nt++)
#pragma unroll
        for (int i = 0; i < 4; i++) oacc[nt][i] = 0.f;
    float mprev[2] = {-1e30f, -1e30f};
    float lsum[2]  = {0.f, 0.f};

    uint4 kpre[4];
    uint2 vpa[4], vpb[4];
#pragma unroll
    for (int j = 0; j < 4; j++) {
        int e = tid + j * 256;
        { int tok = e >> 3, g = e & 7;
          kpre[j] = *(const uint4*)(kg + (long)tok * DHD + 8 * g); }
        { int kpt = e >> 4, d4 = (e & 15) << 2;
          vpa[j] = *(const uint2*)(vg + (long)(2 * kpt) * DHD + d4);
          vpb[j] = *(const uint2*)(vg + (long)(2 * kpt + 1) * DHD + d4); }
    }

    for (int ch = 0; ch < NCH2; ch++) {
        __syncthreads();
#pragma unroll
        for (int j = 0; j < 4; j++) {
            int e = tid + j * 256;
            { int tok = e >> 3, g = e & 7;
              *(uint4*)&Ks[tok * 32 + 4 * (g ^ (tok & 7))] = kpre[j]; }
            { int kpt = e >> 4, d4 = (e & 15) << 2;
              uint4 w;
              w.x = prmtb(vpa[j].x, vpb[j].x, 0x5410);
              w.y = prmtb(vpa[j].x, vpb[j].x, 0x7632);
              w.z = prmtb(vpa[j].y, vpb[j].y, 0x5410);
              w.w = prmtb(vpa[j].y, vpb[j].y, 0x7632);
              *(uint4*)&Vs[kpt * 64 + (d4 ^ ((kpt & 3) << 3))] = w; }
        }
        if (ch + 1 < NCH2) {
            const __half* kc = kg + (long)(ch + 1) * SN2 * DHD;
            const __half* vc = vg + (long)(ch + 1) * SN2 * DHD;
#pragma unroll
            for (int j = 0; j < 4; j++) {
                int e = tid + j * 256;
                { int tok = e >> 3, g = e & 7;
                  kpre[j] = *(const uint4*)(kc + (long)tok * DHD + 8 * g); }
                { int kpt = e >> 4, d4 = (e & 15) << 2;
                  vpa[j] = *(const uint2*)(vc + (long)(2 * kpt) * DHD + d4);
                  vpb[j] = *(const uint2*)(vc + (long)(2 * kpt + 1) * DHD + d4); }
            }
        }
        __syncthreads();

        float sacc[4][4];
#pragma unroll
        for (int nt = 0; nt < 4; nt++)
#pragma unroll
            for (int i = 0; i < 4; i++) sacc[nt][i] = 0.f;
#pragma unroll
        for (int s = 0; s < 4; s++) {
            uint32_t bf[4][2];
#pragma unroll
            for (int nt = 0; nt < 4; nt++) {
                int c = warpn * 32 + nt * 8 + lg;
                bf[nt][0] = Ks[c * 32 + lt + 4 * ((2 * s) ^ (c & 7))];
                bf[nt][1] = Ks[c * 32 + lt + 4 * ((2 * s + 1) ^ (c & 7))];
            }
#pragma unroll
            for (int nt = 0; nt < 4; nt++)
                mma_f16(sacc[nt], aq[s], bf[nt]);
        }

#pragma unroll
        for (int half_ = 0; half_ < 2; half_++) {
            float mx = -1e30f;
#pragma unroll
            for (int nt = 0; nt < 4; nt++) {
                mx = fmaxf(mx, sacc[nt][half_ * 2]);
                mx = fmaxf(mx, sacc[nt][half_ * 2 + 1]);
            }
            mx = fmaxf(mx, __shfl_xor_sync(~0u, mx, 1));
            mx = fmaxf(mx, __shfl_xor_sync(~0u, mx, 2));
            if (lt == 0) redm[(warpm * 16 + half_ * 8 + lg) * 4 + warpn] = mx;
        }
        __syncthreads();

        float scale[2];
#pragma unroll
        for (int half_ = 0; half_ < 2; half_++) {
            int row = warpm * 16 + half_ * 8 + lg;
            float mch = fmaxf(fmaxf(redm[row * 4 + 0], redm[row * 4 + 1]),
                              fmaxf(redm[row * 4 + 2], redm[row * 4 + 3]));
            float mnew = fmaxf(mprev[half_], mch);
            scale[half_] = __expf(mprev[half_] - mnew);
            mprev[half_] = mnew;
            float s = 0.f;
#pragma unroll
            for (int nt = 0; nt < 4; nt++) {
                float e0 = __expf(sacc[nt][half_ * 2]     - mnew);
                float e1 = __expf(sacc[nt][half_ * 2 + 1] - mnew);
                sacc[nt][half_ * 2]     = e0;
                sacc[nt][half_ * 2 + 1] = e1;
                s += e0 + e1;
            }
            s += __shfl_xor_sync(~0u, s, 1);
            s += __shfl_xor_sync(~0u, s, 2);
            if (lt == 0) reds[row * 4 + warpn] = s;
#pragma unroll
            for (int nt = 0; nt < 4; nt++) {
                int kp = warpn * 16 + nt * 4 + lt;
                Ps[row * 64 + (kp ^ ((row & 7) << 2))] =
                    h2pack(sacc[nt][half_ * 2], sacc[nt][half_ * 2 + 1]);
            }
        }
        __syncthreads();

#pragma unroll
        for (int half_ = 0; half_ < 2; half_++) {
            int row = warpm * 16 + half_ * 8 + lg;
            lsum[half_] = lsum[half_] * scale[half_]
                        + reds[row * 4 + 0] + reds[row * 4 + 1]
                        + reds[row * 4 + 2] + reds[row * 4 + 3];
        }
#pragma unroll
        for (int nt = 0; nt < 2; nt++) {
            oacc[nt][0] *= scale[0]; oacc[nt][1] *= scale[0];
            oacc[nt][2] *= scale[1]; oacc[nt][3] *= scale[1];
        }

#pragma unroll
        for (int s = 0; s < 8; s++) {
            const int kp0 = s * 8;
            int mr = warpm * 16 + lg;
            uint32_t af[4];
            af[0] = Ps[mr * 64 + ((kp0 + lt) ^ ((mr & 7) << 2))];
            af[1] = Ps[(mr + 8) * 64 + ((kp0 + lt) ^ (((mr + 8) & 7) << 2))];
            af[2] = Ps[mr * 64 + ((kp0 + lt + 4) ^ ((mr & 7) << 2))];
            af[3] = Ps[(mr + 8) * 64 + ((kp0 + lt + 4) ^ (((mr + 8) & 7) << 2))];
            uint32_t bf[2][2];
#pragma unroll
            for (int nt = 0; nt < 2; nt++) {
                int d = warpn * 16 + nt * 8 + lg;
                bf[nt][0] = Vs[(kp0 + lt) * 64 + (d ^ (lt << 3))];
                bf[nt][1] = Vs[(kp0 + lt + 4) * 64 + (d ^ (lt << 3))];
            }
#pragma unroll
            for (int nt = 0; nt < 2; nt++)
                mma_f16(oacc[nt], af, bf[nt]);
        }
    }

    __half* outb = h_a3vT + (long)bh * DHD * MM;
#pragma unroll
    for (int half_ = 0; half_ < 2; half_++) {
        float inv = 1.f / lsum[half_];
        int r = m0 + warpm * 16 + half_ * 8 + lg;
#pragma unroll
        for (int nt = 0; nt < 2; nt++) {
            int d = warpn * 16 + nt * 8 + 2 * lt;
            outb[(long)d * MM + r]       = __float2half(oacc[nt][half_ * 2] * inv);
            outb[(long)(d + 1) * MM + r] = __float2half(oacc[nt][half_ * 2 + 1] * inv);
        }
    }
}

// ---------------- fused LayerNorm + weight conversion ---------------------------
// blocks [0, BB*NN): LayerNorm rows. blocks [BB*NN, BB*NN + 3*DD*DD/256): weights.
__global__ __launch_bounds__(256) void prep_kernel(
    const float* __restrict__ x, const float* __restrict__ w, const float* __restrict__ b,
    const float* __restrict__ wq, const float* __restrict__ wo)
{
    if (blockIdx.x < BB * NN) {
        long row = blockIdx.x;
        const float* xr = x + row * DD;
        int t = threadIdx.x;
        float v0 = xr[t], v1 = xr[t + 256];
        __shared__ float red[32];

        float s = v0 + v1;
        for (int o = 16; o > 0; o >>= 1) s += __shfl_xor_sync(~0u, s, o);
        if ((t & 31) == 0) red[t >> 5] = s;
        __syncthreads();
        if (t < 32) {
            float ss = (t < 8) ? red[t] : 0.f;
            for (int o = 4; o > 0; o >>= 1) ss += __shfl_xor_sync(~0u, ss, o);
            if (t == 0) red[0] = ss;
        }
        __syncthreads();
        float mu = red[0] * (1.f / DD);
        __syncthreads();

        float d0 = v0 - mu, d1 = v1 - mu;
        float q = d0 * d0 + d1 * d1;
        for (int o = 16; o > 0; o >>= 1) q += __shfl_xor_sync(~0u, q, o);
        if ((t & 31) == 0) red[t >> 5] = q;
        __syncthreads();
        if (t < 32) {
            float ss = (t < 8) ? red[t] : 0.f;
            for (int o = 4; o > 0; o >>= 1) ss += __shfl_xor_sync(~0u, ss, o);
            if (t == 0) red[0] = ss;
        }
        __syncthreads();
        float inv = rsqrtf(red[0] * (1.f / DD) + 1e-5f);
        h_xn[row * DD + t]       = __float2half(d0 * inv * w[t]       + b[t]);
        h_xn[row * DD + t + 256] = __float2half(d1 * inv * w[t + 256] + b[t + 256]);
    } else {
        int i = (blockIdx.x - BB * NN) * 256 + threadIdx.x;   // 3*DD*DD
        {
            int n = i / DD, k2 = i % DD;
            h_wqkvT[i] = __float2half(wq[(long)k2 * (3 * DD) + n]);
        }
        if (i < DD * DD) {
            int n = i / DD, k2 = i % DD;
            h_woutT[i] = __float2half(wo[(long)k2 * DD + n]);
        }
    }
}

// ---------------- landmarks (one half2 per thread, 1024 blocks) ----------------
__global__ void landmarks()
{
    long i = (long)blockIdx.x * 256 + threadIdx.x;    // BH*MM*32 d-pairs
    int dp = i & 31; long r = i >> 5;
    int m = r % MM;  int bh = r / MM;
    long base = ((long)bh * NN + m * LLm) * DHD + dp * 2;
    float sq0 = 0.f, sq1 = 0.f, sk0 = 0.f, sk1 = 0.f;
#pragma unroll
    for (int u = 0; u < LLm; u++) {
        float2 fq = __half22float2(*(const __half2*)(h_q + base + u * DHD));
        float2 fk = __half22float2(*(const __half2*)(h_k + base + u * DHD));
        sq0 += fq.x; sq1 += fq.y;
        sk0 += fk.x; sk1 += fk.y;
    }
    long out = ((long)bh * MM + m) * DHD + dp * 2;
    *(uint32_t*)(h_ql + out) = h2pack(sq0 * (1.f / LLm), sq1 * (1.f / LLm));
    *(uint32_t*)(h_kl + out) = h2pack(sk0 * (1.f / LLm), sk1 * (1.f / LLm));
}

// ---------------- pinv init ----------------------------------------------------
__global__ void init_colmax() { g_colmax = 0.f; }

__global__ __launch_bounds__(256) void colmax_kernel()
{
    int bh = blockIdx.x, j = threadIdx.x;
    const __half* a = h_a2 + (long)bh * MM * MM;
    float s = 0.f;
    for (int i = 0; i < MM; i++) s += __half2float(a[i * MM + j]);
    __shared__ float red[32];
    float m = s;
    for (int o = 16; o > 0; o >>= 1) m = fmaxf(m, __shfl_xor_sync(~0u, m, o));
    if ((j & 31) == 0) red[j >> 5] = m;
    __syncthreads();
    if (j < 32) {
        float m2 = (j < 8) ? red[j] : -1e30f;
        for (int o = 4; o > 0; o >>= 1) m2 = fmaxf(m2, __shfl_xor_sync(~0u, m2, o));
        if (j == 0) atomicMax((int*)&g_colmax, __float_as_int(m2));
    }
}

__global__ void zinit()
{
    long i = (long)blockIdx.x * 256 + threadIdx.x;
    int col = i % MM; long r = i / MM;
    int row = r % MM; int bh = r / MM;
    float inv = 1.f / g_colmax;
    h_zT[i] = __float2half(__half2float(h_a2[i]) * inv);
    h_z [i] = __float2half(__half2float(h_a2[((long)bh * MM + col) * MM + row]) * inv);
}

// ---------------- fused reshape + depthwise conv (all half) --------------------
__global__ void att_conv(const float* __restrict__ rw)
{
    long i = (long)blockIdx.x * 256 + threadIdx.x;
    int dq = i % 16; long r = i / 16;
    int h = r % HH;  long r2 = r / HH;
    int n = r2 % NN; int b = r2 / NN;
    long bhbase = (long)(b * HH + h) * NN;
    const __half* vb = h_v + bhbase * DHD;
    uint2 ov = *(const uint2*)(h_o + (bhbase + n) * DHD + dq * 4);
    float2 o0 = __half22float2(*(const __half2*)&ov.x);
    float2 o1 = __half22float2(*(const __half2*)&ov.y);
    float a0 = o0.x, a1 = o0.y, a2 = o1.x, a3 = o1.y;
#pragma unroll
    for (int j = 0; j < KC; j++) {
        int tt = n + j - KC / 2;
        if (tt >= 0 && tt < NN) {
            float w = rw[h * KC + j];
            uint2 vv = *(const uint2*)(vb + (long)tt * DHD + dq * 4);
            float2 v0 = __half22float2(*(const __half2*)&vv.x);
            float2 v1 = __half22float2(*(const __half2*)&vv.y);
            a0 += w * v0.x; a1 += w * v0.y; a2 += w * v1.x; a3 += w * v1.y;
        }
    }
    uint2 w2;
    w2.x = h2pack(a0, a1);
    w2.y = h2pack(a2, a3);
    *(uint2*)&h_att[((long)(b * NN + n)) * DD + h * DHD + dq * 4] = w2;
}

// ---------------- host orchestration -------------------------------------------
extern "C" void kernel_launch(void* const* d_in, const int* in_sizes, int n_in,
                              void* d_out, int out_size)
{
    const float* x      = (const float*)d_in[0];
    const float* norm_w = (const float*)d_in[1];
    const float* norm_b = (const float*)d_in[2];
    const float* w_qkv  = (const float*)d_in[3];
    const float* w_out  = (const float*)d_in[4];
    const float* b_out  = (const float*)d_in[5];
    const float* res_w  = (const float*)d_in[6];
    float* y = (float*)d_out;

    __half *p_xn, *p_wqkvT, *p_woutT, *p_q, *p_k, *p_v, *p_ql, *p_kl;
    __half *p_a2, *p_z, *p_zT, *p_z2, *p_z2T, *p_xz, *p_t1T, *p_t2T, *p_a3vT, *p_WT, *p_att;
    cudaGetSymbolAddress((void**)&p_xn,   h_xn);
    cudaGetSymbolAddress((void**)&p_wqkvT,h_wqkvT);
    cudaGetSymbolAddress((void**)&p_woutT,h_woutT);
    cudaGetSymbolAddress((void**)&p_q,    h_q);
    cudaGetSymbolAddress((void**)&p_k,    h_k);
    cudaGetSymbolAddress((void**)&p_v,    h_v);
    cudaGetSymbolAddress((void**)&p_ql,   h_ql);
    cudaGetSymbolAddress((void**)&p_kl,   h_kl);
    cudaGetSymbolAddress((void**)&p_a2,   h_a2);
    cudaGetSymbolAddress((void**)&p_z,    h_z);
    cudaGetSymbolAddress((void**)&p_zT,   h_zT);
    cudaGetSymbolAddress((void**)&p_z2,   h_z2);
    cudaGetSymbolAddress((void**)&p_z2T,  h_z2T);
    cudaGetSymbolAddress((void**)&p_xz,   h_xz);
    cudaGetSymbolAddress((void**)&p_t1T,  h_t1T);
    cudaGetSymbolAddress((void**)&p_t2T,  h_t2T);
    cudaGetSymbolAddress((void**)&p_a3vT, h_a3vT);
    cudaGetSymbolAddress((void**)&p_WT,   h_WT);
    cudaGetSymbolAddress((void**)&p_att,  h_att);

    const long MM2 = (long)MM * MM;
    void* nul = nullptr;

    // 1. LayerNorm + weight conversion (single launch)
    prep_kernel<<<BB * NN + (3 * DD * DD) / 256, 256>>>(
        x, norm_w, norm_b, w_qkv, w_out);
    // 2. qkv GEMM with fused split
    gemm_h<128, 1><<<dim3((3 * DD) / 128, (BB * NN) / 128, 1), 256>>>(
        p_xn, p_wqkvT, p_q, p_k, p_v,
        BB * NN, 3 * DD, DD, 0, 0, 0, 1.f, 0.f);
    // 3. landmarks
    landmarks<<<(BH * MM * 32) / 256, 256>>>();
    // 4. a2 = softmax(ql @ kl^T)
    sim_softmax_h<<<dim3(MM / 64, 1, BH), 256>>>(
        p_ql, p_kl, p_a2, (long)MM * DHD, (long)MM * DHD, MM2);
    // 5. pinv init
    init_colmax<<<1, 1>>>();
    colmax_kernel<<<BH, 256>>>();
    zinit<<<(int)((long)BH * MM * MM / 256), 256>>>();
    // 6. Newton-Schulz
    __half *zin = p_z, *zinT = p_zT, *zout = p_z2, *zoutT = p_z2T;
    for (int it = 0; it < NITER; it++) {
        gemm_h<64, 3><<<dim3(MM / 64, MM / 128, BH), 256>>>(
            p_a2, zinT, p_xz, nul, p_t1T, MM, MM, MM, MM2, MM2, MM2, 1.f, 7.f);
        gemm_h<64, 3><<<dim3(MM / 64, MM / 128, BH), 256>>>(
            p_xz, p_t1T, nul, nul, p_t2T, MM, MM, MM, MM2, MM2, MM2, 1.f, 15.f);
        gemm_h<64, 3><<<dim3(MM / 64, MM / 128, BH), 256>>>(
            p_xz, p_t2T, nul, nul, p_t1T, MM, MM, MM, MM2, MM2, MM2, 1.f, 13.f);
        gemm_h<64, 3><<<dim3(MM / 64, MM / 128, BH), 256>>>(
            zin, p_t1T, zout, zoutT, nul, MM, MM, MM, MM2, MM2, MM2, 0.25f, 0.f);
        __half* t;
        t = zin;  zin  = zout;  zout  = t;
        t = zinT; zinT = zoutT; zoutT = t;
    }
    // 7. a3vT = (softmax(ql @ k^T) @ v)^T  (flash)
    a3v_flash_h<<<dim3(MM / 32, 1, BH), 256>>>();
    // 8. WT = (z @ a3v)^T
    gemm_h<64, 3><<<dim3(1, MM / 128, BH), 256>>>(
        zin, p_a3vT, nul, p_WT, nul, MM, DHD, MM,
        MM2, (long)DHD * MM, (long)DHD * MM, 1.f, 0.f);
    // 9. o = softmax(q @ kl^T) @ W  (fully fused)
    sim_out_h<<<dim3(NN / 64, 1, BH), 256>>>();
    // 10. att = reshape(o) + conv(v)
    att_conv<<<(BB * NN * HH * 16) / 256, 256>>>(res_w);
    // 11. y = att @ w_out + x + b_out
    gemm_h<128, 2><<<dim3(DD / 128, (BB * NN) / 128, 1), 256>>>(
        p_att, p_woutT, y, (void*)x, (void*)b_out,
        BB * NN, DD, DD, 0, 0, 0, 1.f, 0.f);
}

// round 16
// speedup vs baseline: 1.0499x; 1.0354x over previous
#include <cuda_runtime.h>
#include <cuda_fp16.h>
#include <cstdint>

#define BB 4
#define NN 4096
#define DD 512
#define HH 8
#define DHD 64
#define MM 256
#define LLm 16
#define NITER 6
#define KC 33
#define BH (BB*HH)
#define SN2 128
#define NCH2 (NN/SN2)

// ---------------- scratch -------------------------------------------------------
__device__ __align__(16) __half h_xn   [BB*NN*DD];
__device__ __align__(16) __half h_wqkvT[3*DD*DD];
__device__ __align__(16) __half h_woutT[DD*DD];
__device__ __align__(16) __half h_q  [BH*NN*DHD];
__device__ __align__(16) __half h_k  [BH*NN*DHD];
__device__ __align__(16) __half h_v  [BH*NN*DHD];
__device__ __align__(16) __half h_o  [BH*NN*DHD];
__device__ __align__(16) __half h_ql [BH*MM*DHD];
__device__ __align__(16) __half h_kl [BH*MM*DHD];
__device__ __align__(16) __half h_a2 [BH*MM*MM];
__device__ __align__(16) __half h_z  [BH*MM*MM];
__device__ __align__(16) __half h_zT [BH*MM*MM];
__device__ __align__(16) __half h_z2 [BH*MM*MM];
__device__ __align__(16) __half h_z2T[BH*MM*MM];
__device__ __align__(16) __half h_xz [BH*MM*MM];
__device__ __align__(16) __half h_t1T[BH*MM*MM];
__device__ __align__(16) __half h_t2T[BH*MM*MM];
__device__ __align__(16) __half h_a3vT[BH*DHD*MM];    // [d][m]
__device__ __align__(16) __half h_WT [BH*DHD*MM];     // [d][m]
__device__ __align__(16) __half h_att[BB*NN*DD];
__device__ float g_colmax;

// ---------------- helpers ------------------------------------------------------
__device__ __forceinline__ uint32_t h2pack(float a, float b) {
    __half2 h = __floats2half2_rn(a, b);
    return *reinterpret_cast<uint32_t*>(&h);
}
__device__ __forceinline__ uint32_t prmtb(uint32_t a, uint32_t b, uint32_t sel) {
    uint32_t d;
    asm("prmt.b32 %0, %1, %2, %3;" : "=r"(d) : "r"(a), "r"(b), "r"(sel));
    return d;
}
__device__ __forceinline__ void mma_f16(float* c, const uint32_t* a, const uint32_t* b) {
    asm volatile(
        "mma.sync.aligned.m16n8k16.row.col.f32.f16.f16.f32 "
        "{%0,%1,%2,%3}, {%4,%5,%6,%7}, {%8,%9}, {%0,%1,%2,%3};"
        : "+f"(c[0]), "+f"(c[1]), "+f"(c[2]), "+f"(c[3])
        : "r"(a[0]), "r"(a[1]), "r"(a[2]), "r"(a[3]), "r"(b[0]), "r"(b[1]));
}
__device__ __forceinline__ void ldsm4(uint32_t* r, uint32_t saddr) {
    asm volatile("ldmatrix.sync.aligned.m8n8.x4.shared.b16 {%0,%1,%2,%3}, [%4];"
        : "=r"(r[0]), "=r"(r[1]), "=r"(r[2]), "=r"(r[3]) : "r"(saddr));
}
__device__ __forceinline__ void ldsm2(uint32_t* r, uint32_t saddr) {
    asm volatile("ldmatrix.sync.aligned.m8n8.x2.shared.b16 {%0,%1}, [%2];"
        : "=r"(r[0]), "=r"(r[1]) : "r"(saddr));
}
__device__ __forceinline__ void cpa16(uint32_t dst, const void* src) {
    asm volatile("cp.async.cg.shared.global [%0], [%1], 16;" :: "r"(dst), "l"(src));
}
#define CP_COMMIT() asm volatile("cp.async.commit_group;")

// =============================================================================
// gemm_h: C = alpha * A @ B^T, A [M][K] half, B [N][K] half (both k-contig).
// BM=128, BN template, BK=32. 2-stage cp.async + LDSM (proven form).
// 8 warps 4m x 2n.
// MODE 0: p0 = float* C ; MODE 1: qkv split ; MODE 2: y = acc + x + bout
// MODE 3: p0 Cn(half normal), p1 CtRaw(half transp), p2 CtDiag(half transp, dgI-acc)
// =============================================================================
template<int BN, int MODE>
__global__ __launch_bounds__(256, 2) void gemm_h(
    const __half* __restrict__ Ag, const __half* __restrict__ Bg,
    void* __restrict__ p0, void* __restrict__ p1, void* __restrict__ p2,
    int Md, int Nd, int Kd, long sA, long sB, long sC,
    float alpha, float dg)
{
    constexpr int NT = BN / 16;
    constexpr int WN = BN / 2;
    constexpr int NBJ = BN / 64;

    __shared__ uint32_t As[2][128 * 16];
    __shared__ uint32_t Bs[2][BN * 16];

    const __half* A = Ag + (long)blockIdx.z * sA;
    const __half* Bp = Bg + (long)blockIdx.z * sB;
    const int m0 = blockIdx.y * 128;
    const int n0 = blockIdx.x * BN;
    const int tid = threadIdx.x;
    const int wid = tid >> 5, lane = tid & 31;
    const int warpm = wid & 3, warpn = wid >> 2;
    const int lg = lane >> 2, lt = lane & 3;

    const uint32_t asmb = (uint32_t)__cvta_generic_to_shared(&As[0][0]);
    const uint32_t bsmb = (uint32_t)__cvta_generic_to_shared(&Bs[0][0]);

    const int t4  = lane >> 3;
    const int agh = t4 >> 1;
    int aoff[2], asw[2];
#pragma unroll
    for (int mt = 0; mt < 2; mt++) {
        int rr = warpm * 32 + mt * 16 + (t4 & 1) * 8 + (lane & 7);
        aoff[mt] = rr * 64;
        asw[mt]  = (rr >> 1) & 3;
    }
    const int btb = t4 & 1;
    int boff[NT], bsw[NT];
#pragma unroll
    for (int nt = 0; nt < NT; nt++) {
        int n = warpn * WN + nt * 8 + (lane & 7);
        boff[nt] = n * 64;
        bsw[nt]  = (n >> 1) & 3;
    }

    float acc[2][NT][4];
#pragma unroll
    for (int mt = 0; mt < 2; mt++)
#pragma unroll
        for (int nt = 0; nt < NT; nt++)
#pragma unroll
            for (int i = 0; i < 4; i++) acc[mt][nt][i] = 0.f;

    const int nk = Kd >> 5;

#define LOADT(kt, st) do {                                                      \
    const int k0_ = (kt) << 5;                                                  \
    _Pragma("unroll")                                                           \
    for (int j = 0; j < 2; j++) {                                               \
        int e = tid + j * 256;                                                  \
        int row = e >> 2, g = e & 3;                                            \
        uint32_t d = asmb + (uint32_t)(((st) * 2048 + row * 16 +                \
                     4 * (g ^ ((row >> 1) & 3))) << 2);                         \
        cpa16(d, A + (long)(m0 + row) * Kd + k0_ + 8 * g);                      \
    }                                                                           \
    _Pragma("unroll")                                                           \
    for (int j = 0; j < NBJ; j++) {                                             \
        int e = tid + j * 256;                                                  \
        int n = e >> 2, g = e & 3;                                              \
        uint32_t d = bsmb + (uint32_t)(((st) * (BN * 16) + n * 16 +             \
                     4 * (g ^ ((n >> 1) & 3))) << 2);                           \
        cpa16(d, Bp + (long)(n0 + n) * Kd + k0_ + 8 * g);                       \
    }                                                                           \
    CP_COMMIT();                                                                \
} while (0)

    LOADT(0, 0);

    for (int kt = 0; kt < nk; kt++) {
        const int st = kt & 1;
        if (kt + 1 < nk) {
            LOADT(kt + 1, st ^ 1);
            asm volatile("cp.async.wait_group 1;");
        } else {
            asm volatile("cp.async.wait_group 0;");
        }
        __syncthreads();

        const uint32_t a_base = asmb + (uint32_t)((st * 2048) << 2);
        const uint32_t b_base = bsmb + (uint32_t)((st * (BN * 16)) << 2);
#pragma unroll
        for (int s = 0; s < 2; s++) {
            uint32_t af[2][4], bf[NT][2];
#pragma unroll
            for (int mt = 0; mt < 2; mt++)
                ldsm4(af[mt], a_base + (uint32_t)((aoff[mt] +
                      ((((s << 1) | agh) ^ asw[mt]) << 4))));
#pragma unroll
            for (int nt = 0; nt < NT; nt++)
                ldsm2(bf[nt], b_base + (uint32_t)((boff[nt] +
                      ((((s << 1) | btb) ^ bsw[nt]) << 4))));
#pragma unroll
            for (int mt = 0; mt < 2; mt++)
#pragma unroll
                for (int nt = 0; nt < NT; nt++)
                    mma_f16(acc[mt][nt], af[mt], bf[nt]);
        }
        __syncthreads();
    }
#undef LOADT

    if (MODE == 0) {
        float* C = (float*)p0 + (long)blockIdx.z * sC;
#pragma unroll
        for (int mt = 0; mt < 2; mt++)
#pragma unroll
            for (int nt = 0; nt < NT; nt++) {
                int r = m0 + warpm * 32 + mt * 16 + lg;
                int c = n0 + warpn * WN + nt * 8 + 2 * lt;
                *(float2*)(C + (long)r * Nd + c) =
                    make_float2(acc[mt][nt][0] * alpha, acc[mt][nt][1] * alpha);
                *(float2*)(C + (long)(r + 8) * Nd + c) =
                    make_float2(acc[mt][nt][2] * alpha, acc[mt][nt][3] * alpha);
            }
    } else if (MODE == 1) {
        __half* qh = (__half*)p0; __half* kh = (__half*)p1; __half* vh = (__half*)p2;
#pragma unroll
        for (int mt = 0; mt < 2; mt++)
#pragma unroll
            for (int nt = 0; nt < NT; nt++) {
                int c = n0 + warpn * WN + nt * 8 + 2 * lt;
                int which = c >> 9, cc = c & 511;
                int h = cc >> 6, d = cc & 63;
                float sc = (which == 0) ? 0.125f : 1.f;
                __half* dsth = (which == 0) ? qh : (which == 1) ? kh : vh;
#pragma unroll
                for (int half_ = 0; half_ < 2; half_++) {
                    int m = m0 + warpm * 32 + mt * 16 + half_ * 8 + lg;
                    int b = m >> 12, n = m & 4095;
                    long dst = ((long)(b * HH + h) * NN + n) * DHD + d;
                    *(uint32_t*)(dsth + dst) = h2pack(acc[mt][nt][half_ * 2] * sc,
                                                      acc[mt][nt][half_ * 2 + 1] * sc);
                }
            }
    } else if (MODE == 2) {
        float* y = (float*)p0;
        const float* xp = (const float*)p1;
        const float* bp = (const float*)p2;
#pragma unroll
        for (int mt = 0; mt < 2; mt++)
#pragma unroll
            for (int nt = 0; nt < NT; nt++) {
                int r = m0 + warpm * 32 + mt * 16 + lg;
                int c = n0 + warpn * WN + nt * 8 + 2 * lt;
                float b0 = bp[c], b1 = bp[c + 1];
                float2 x0 = *(const float2*)(xp + (long)r * Nd + c);
                float2 x1 = *(const float2*)(xp + (long)(r + 8) * Nd + c);
                *(float2*)(y + (long)r * Nd + c) =
                    make_float2(acc[mt][nt][0] + x0.x + b0, acc[mt][nt][1] + x0.y + b1);
                *(float2*)(y + (long)(r + 8) * Nd + c) =
                    make_float2(acc[mt][nt][2] + x1.x + b0, acc[mt][nt][3] + x1.y + b1);
            }
    } else {
        __half* Cn = p0 ? (__half*)p0 + (long)blockIdx.z * sC : nullptr;
        __half* Ctr = p1 ? (__half*)p1 + (long)blockIdx.z * sC : nullptr;
        __half* Ctd = p2 ? (__half*)p2 + (long)blockIdx.z * sC : nullptr;
#pragma unroll
        for (int mt = 0; mt < 2; mt++)
#pragma unroll
            for (int nt = 0; nt < NT; nt++) {
                int r = m0 + warpm * 32 + mt * 16 + lg;
                int c = n0 + warpn * WN + nt * 8 + 2 * lt;
                float v00 = acc[mt][nt][0] * alpha;
                float v01 = acc[mt][nt][1] * alpha;
                float v10 = acc[mt][nt][2] * alpha;
                float v11 = acc[mt][nt][3] * alpha;
                if (Cn) {
                    *(uint32_t*)(Cn + (long)r * Nd + c)       = h2pack(v00, v01);
                    *(uint32_t*)(Cn + (long)(r + 8) * Nd + c) = h2pack(v10, v11);
                }
                if (Ctr) {
                    Ctr[(long)c * Md + r]           = __float2half(v00);
                    Ctr[(long)(c + 1) * Md + r]     = __float2half(v01);
                    Ctr[(long)c * Md + r + 8]       = __float2half(v10);
                    Ctr[(long)(c + 1) * Md + r + 8] = __float2half(v11);
                }
                if (Ctd) {
                    Ctd[(long)c * Md + r]           = __float2half(((r == c)         ? dg : 0.f) - v00);
                    Ctd[(long)(c + 1) * Md + r]     = __float2half(((r == c + 1)     ? dg : 0.f) - v01);
                    Ctd[(long)c * Md + r + 8]       = __float2half(((r + 8 == c)     ? dg : 0.f) - v10);
                    Ctd[(long)(c + 1) * Md + r + 8] = __float2half(((r + 8 == c + 1) ? dg : 0.f) - v11);
                }
            }
    }
}

// =============================================================================
// sim_softmax_h: Out(half) = softmax_row(A @ B^T)  (used for a2 only)
// =============================================================================
__global__ __launch_bounds__(256, 2) void sim_softmax_h(
    const __half* __restrict__ Ag, const __half* __restrict__ Bg,
    __half* __restrict__ Og, long sA, long sB, long sO)
{
    __shared__ uint32_t As[64 * 16];
    __shared__ uint32_t Bs[256 * 16];
    __shared__ float redm[64 * 4];
    __shared__ float reds[64 * 4];

    const __half* A = Ag + (long)blockIdx.z * sA;
    const __half* B = Bg + (long)blockIdx.z * sB;
    __half*       O = Og + (long)blockIdx.z * sO;
    const int m0 = blockIdx.x * 64;
    const int tid = threadIdx.x;
    const int wid = tid >> 5, lane = tid & 31;
    const int warpm = wid & 1, warpn = wid >> 1;
    const int lg = lane >> 2, lt = lane & 3;

    const uint32_t asmb = (uint32_t)__cvta_generic_to_shared(&As[0]);
    const uint32_t bsmb = (uint32_t)__cvta_generic_to_shared(&Bs[0]);

    const int t4  = lane >> 3;
    const int agh = t4 >> 1;
    int aoff[2], asw[2];
#pragma unroll
    for (int mt = 0; mt < 2; mt++) {
        int rr = warpm * 32 + mt * 16 + (t4 & 1) * 8 + (lane & 7);
        aoff[mt] = rr * 64;
        asw[mt]  = (rr >> 1) & 3;
    }
    const int btb = t4 & 1;
    int boff[8], bsw[8];
#pragma unroll
    for (int nt = 0; nt < 8; nt++) {
        int n = warpn * 64 + nt * 8 + (lane & 7);
        boff[nt] = n * 64;
        bsw[nt]  = (n >> 1) & 3;
    }

    float acc[2][8][4];
#pragma unroll
    for (int mt = 0; mt < 2; mt++)
#pragma unroll
        for (int nt = 0; nt < 8; nt++)
#pragma unroll
            for (int i = 0; i < 4; i++) acc[mt][nt][i] = 0.f;

#pragma unroll
    for (int kt = 0; kt < 2; kt++) {
        const int k0 = kt * 32;
        {
            int row = tid >> 2, g = tid & 3;
            uint4 va = *(const uint4*)(A + (long)(m0 + row) * DHD + k0 + 8 * g);
            *(uint4*)&As[row * 16 + 4 * (g ^ ((row >> 1) & 3))] = va;
        }
#pragma unroll
        for (int j = 0; j < 4; j++) {
            int e = tid + j * 256;
            int n = e >> 2, g = e & 3;
            uint4 vb = *(const uint4*)(B + (long)n * DHD + k0 + 8 * g);
            *(uint4*)&Bs[n * 16 + 4 * (g ^ ((n >> 1) & 3))] = vb;
        }
        __syncthreads();

#pragma unroll
        for (int s = 0; s < 2; s++) {
            uint32_t af[2][4], bf[8][2];
#pragma unroll
            for (int mt = 0; mt < 2; mt++)
                ldsm4(af[mt], asmb + (uint32_t)(aoff[mt] +
                      ((((s << 1) | agh) ^ asw[mt]) << 4)));
#pragma unroll
            for (int nt = 0; nt < 8; nt++)
                ldsm2(bf[nt], bsmb + (uint32_t)(boff[nt] +
                      ((((s << 1) | btb) ^ bsw[nt]) << 4)));
#pragma unroll
            for (int mt = 0; mt < 2; mt++)
#pragma unroll
                for (int nt = 0; nt < 8; nt++)
                    mma_f16(acc[mt][nt], af[mt], bf[nt]);
        }
        __syncthreads();
    }

#pragma unroll
    for (int mt = 0; mt < 2; mt++)
#pragma unroll
        for (int half_ = 0; half_ < 2; half_++) {
            float mx = -1e30f;
#pragma unroll
            for (int nt = 0; nt < 8; nt++) {
                mx = fmaxf(mx, acc[mt][nt][half_ * 2]);
                mx = fmaxf(mx, acc[mt][nt][half_ * 2 + 1]);
            }
            mx = fmaxf(mx, __shfl_xor_sync(~0u, mx, 1));
            mx = fmaxf(mx, __shfl_xor_sync(~0u, mx, 2));
            int rloc = warpm * 32 + mt * 16 + half_ * 8 + lg;
            if (lt == 0) redm[rloc * 4 + warpn] = mx;
        }
    __syncthreads();
#pragma unroll
    for (int mt = 0; mt < 2; mt++)
#pragma unroll
        for (int half_ = 0; half_ < 2; half_++) {
            int rloc = warpm * 32 + mt * 16 + half_ * 8 + lg;
            float m4 = fmaxf(fmaxf(redm[rloc * 4 + 0], redm[rloc * 4 + 1]),
                             fmaxf(redm[rloc * 4 + 2], redm[rloc * 4 + 3]));
            float s = 0.f;
#pragma unroll
            for (int nt = 0; nt < 8; nt++) {
                float e0 = __expf(acc[mt][nt][half_ * 2]     - m4);
                float e1 = __expf(acc[mt][nt][half_ * 2 + 1] - m4);
                acc[mt][nt][half_ * 2]     = e0;
                acc[mt][nt][half_ * 2 + 1] = e1;
                s += e0 + e1;
            }
            s += __shfl_xor_sync(~0u, s, 1);
            s += __shfl_xor_sync(~0u, s, 2);
            if (lt == 0) reds[rloc * 4 + warpn] = s;
        }
    __syncthreads();
#pragma unroll
    for (int mt = 0; mt < 2; mt++)
#pragma unroll
        for (int half_ = 0; half_ < 2; half_++) {
            int rloc = warpm * 32 + mt * 16 + half_ * 8 + lg;
            float tot = reds[rloc * 4 + 0] + reds[rloc * 4 + 1]
                      + reds[rloc * 4 + 2] + reds[rloc * 4 + 3];
            float inv = 1.f / tot;
            int r = m0 + rloc;
#pragma unroll
            for (int nt = 0; nt < 8; nt++) {
                int c = warpn * 64 + nt * 8 + 2 * lt;
                *(uint32_t*)(O + (long)r * MM + c) =
                    h2pack(acc[mt][nt][half_ * 2] * inv, acc[mt][nt][half_ * 2 + 1] * inv);
            }
        }
}

// =============================================================================
// sim_out_h: o = softmax_row(q @ kl^T) @ W, fully fused (a1 never materialized).
// =============================================================================
__global__ __launch_bounds__(256, 2) void sim_out_h()
{
    __shared__ uint32_t S[8192];
    __shared__ float redm[64 * 4];
    __shared__ float reds[64 * 4];

    const int bh = blockIdx.z;
    const __half* A = h_q  + (long)bh * NN * DHD;
    const __half* B = h_kl + (long)bh * MM * DHD;
    const __half* WTb = h_WT + (long)bh * DHD * MM;
    const int m0 = blockIdx.x * 64;
    const int tid = threadIdx.x;
    const int wid = tid >> 5, lane = tid & 31;
    const int warpm = wid & 1, warpn = wid >> 1;
    const int lg = lane >> 2, lt = lane & 3;

    uint32_t* As = S;
    uint32_t* Bs = S + 1024;
    const uint32_t asmb = (uint32_t)__cvta_generic_to_shared(As);
    const uint32_t bsmb = (uint32_t)__cvta_generic_to_shared(Bs);

    const int t4  = lane >> 3;
    const int agh = t4 >> 1;
    int aoff[2], asw[2];
#pragma unroll
    for (int mt = 0; mt < 2; mt++) {
        int rr = warpm * 32 + mt * 16 + (t4 & 1) * 8 + (lane & 7);
        aoff[mt] = rr * 64;
        asw[mt]  = (rr >> 1) & 3;
    }
    const int btb = t4 & 1;
    int boff[8], bsw[8];
#pragma unroll
    for (int nt = 0; nt < 8; nt++) {
        int n = warpn * 64 + nt * 8 + (lane & 7);
        boff[nt] = n * 64;
        bsw[nt]  = (n >> 1) & 3;
    }

    float acc[2][8][4];
#pragma unroll
    for (int mt = 0; mt < 2; mt++)
#pragma unroll
        for (int nt = 0; nt < 8; nt++)
#pragma unroll
            for (int i = 0; i < 4; i++) acc[mt][nt][i] = 0.f;

#pragma unroll
    for (int kt = 0; kt < 2; kt++) {
        const int k0 = kt * 32;
        {
            int row = tid >> 2, g = tid & 3;
            uint4 va = *(const uint4*)(A + (long)(m0 + row) * DHD + k0 + 8 * g);
            *(uint4*)&As[row * 16 + 4 * (g ^ ((row >> 1) & 3))] = va;
        }
#pragma unroll
        for (int j = 0; j < 4; j++) {
            int e = tid + j * 256;
            int n = e >> 2, g = e & 3;
            uint4 vb = *(const uint4*)(B + (long)n * DHD + k0 + 8 * g);
            *(uint4*)&Bs[n * 16 + 4 * (g ^ ((n >> 1) & 3))] = vb;
        }
        __syncthreads();

#pragma unroll
        for (int s = 0; s < 2; s++) {
            uint32_t af[2][4], bf[8][2];
#pragma unroll
            for (int mt = 0; mt < 2; mt++)
                ldsm4(af[mt], asmb + (uint32_t)(aoff[mt] +
                      ((((s << 1) | agh) ^ asw[mt]) << 4)));
#pragma unroll
            for (int nt = 0; nt < 8; nt++)
                ldsm2(bf[nt], bsmb + (uint32_t)(boff[nt] +
                      ((((s << 1) | btb) ^ bsw[nt]) << 4)));
#pragma unroll
            for (int mt = 0; mt < 2; mt++)
#pragma unroll
                for (int nt = 0; nt < 8; nt++)
                    mma_f16(acc[mt][nt], af[mt], bf[nt]);
        }
        __syncthreads();
    }

#pragma unroll
    for (int mt = 0; mt < 2; mt++)
#pragma unroll
        for (int half_ = 0; half_ < 2; half_++) {
            float mx = -1e30f;
#pragma unroll
            for (int nt = 0; nt < 8; nt++) {
                mx = fmaxf(mx, acc[mt][nt][half_ * 2]);
                mx = fmaxf(mx, acc[mt][nt][half_ * 2 + 1]);
            }
            mx = fmaxf(mx, __shfl_xor_sync(~0u, mx, 1));
            mx = fmaxf(mx, __shfl_xor_sync(~0u, mx, 2));
            int rloc = warpm * 32 + mt * 16 + half_ * 8 + lg;
            if (lt == 0) redm[rloc * 4 + warpn] = mx;
        }
    __syncthreads();
#pragma unroll
    for (int mt = 0; mt < 2; mt++)
#pragma unroll
        for (int half_ = 0; half_ < 2; half_++) {
            int rloc = warpm * 32 + mt * 16 + half_ * 8 + lg;
            float m4 = fmaxf(fmaxf(redm[rloc * 4 + 0], redm[rloc * 4 + 1]),
                             fmaxf(redm[rloc * 4 + 2], redm[rloc * 4 + 3]));
            float s = 0.f;
#pragma unroll
            for (int nt = 0; nt < 8; nt++) {
                float e0 = __expf(acc[mt][nt][half_ * 2]     - m4);
                float e1 = __expf(acc[mt][nt][half_ * 2 + 1] - m4);
                acc[mt][nt][half_ * 2]     = e0;
                acc[mt][nt][half_ * 2 + 1] = e1;
                s += e0 + e1;
            }
            s += __shfl_xor_sync(~0u, s, 1);
            s += __shfl_xor_sync(~0u, s, 2);
            if (lt == 0) reds[rloc * 4 + warpn] = s;
        }
    __syncthreads();
#pragma unroll
    for (int mt = 0; mt < 2; mt++)
#pragma unroll
        for (int half_ = 0; half_ < 2; half_++) {
            int rloc = warpm * 32 + mt * 16 + half_ * 8 + lg;
            float tot = reds[rloc * 4 + 0] + reds[rloc * 4 + 1]
                      + reds[rloc * 4 + 2] + reds[rloc * 4 + 3];
            float inv = 1.f / tot;
#pragma unroll
            for (int nt = 0; nt < 8; nt++) {
                int kp = warpn * 32 + nt * 4 + lt;
                S[rloc * 128 + (kp ^ ((rloc & 7) << 2))] =
                    h2pack(acc[mt][nt][half_ * 2] * inv, acc[mt][nt][half_ * 2 + 1] * inv);
            }
        }
    __syncthreads();

    float oacc[2][2][4];
#pragma unroll
    for (int mt = 0; mt < 2; mt++)
#pragma unroll
        for (int nt = 0; nt < 2; nt++)
#pragma unroll
            for (int i = 0; i < 4; i++) oacc[mt][nt][i] = 0.f;

#pragma unroll
    for (int s = 0; s < 16; s++) {
        const int kp0 = s * 8;
        uint32_t af[2][4], bf[2][2];
#pragma unroll
        for (int mt = 0; mt < 2; mt++) {
            int mr = warpm * 32 + mt * 16 + lg;
            af[mt][0] = S[mr * 128 + ((kp0 + lt) ^ ((mr & 7) << 2))];
            af[mt][1] = S[(mr + 8) * 128 + ((kp0 + lt) ^ (((mr + 8) & 7) << 2))];
            af[mt][2] = S[mr * 128 + ((kp0 + lt + 4) ^ ((mr & 7) << 2))];
            af[mt][3] = S[(mr + 8) * 128 + ((kp0 + lt + 4) ^ (((mr + 8) & 7) << 2))];
        }
#pragma unroll
        for (int nt = 0; nt < 2; nt++) {
            int d = warpn * 16 + nt * 8 + lg;
            bf[nt][0] = *(const uint32_t*)(WTb + (long)d * MM + s * 16 + 2 * lt);
            bf[nt][1] = *(const uint32_t*)(WTb + (long)d * MM + s * 16 + 8 + 2 * lt);
        }
#pragma unroll
        for (int mt = 0; mt < 2; mt++)
#pragma unroll
            for (int nt = 0; nt < 2; nt++)
                mma_f16(oacc[mt][nt], af[mt], bf[nt]);
    }

    __half* ob = h_o + (long)bh * NN * DHD;
#pragma unroll
    for (int mt = 0; mt < 2; mt++)
#pragma unroll
        for (int half_ = 0; half_ < 2; half_++) {
            int r = m0 + warpm * 32 + mt * 16 + half_ * 8 + lg;
#pragma unroll
            for (int nt = 0; nt < 2; nt++) {
                int d = warpn * 16 + nt * 8 + 2 * lt;
                *(uint32_t*)(ob + (long)r * DHD + d) =
                    h2pack(oacc[mt][nt][half_ * 2], oacc[mt][nt][half_ * 2 + 1]);
            }
        }
}

// =============================================================================
// a3v_flash_h: a3vT = (softmax_row(ql @ k^T) @ v)^T, SN2=128 chunks.
// =============================================================================
__global__ __launch_bounds__(256, 2) void a3v_flash_h()
{
    __shared__ uint32_t Ks[128 * 32];
    __shared__ uint32_t Vs[64 * 64];
    __shared__ uint32_t Ps[32 * 64];
    __shared__ float redm[32 * 4];
    __shared__ float reds[32 * 4];

    const int bh = blockIdx.z;
    const int m0 = blockIdx.x * 32;
    const __half* ql = h_ql + (long)bh * MM * DHD;
    const __half* kg = h_k  + (long)bh * NN * DHD;
    const __half* vg = h_v  + (long)bh * NN * DHD;

    const int tid = threadIdx.x;
    const int wid = tid >> 5, lane = tid & 31;
    const int warpm = wid & 1, warpn = wid >> 1;
    const int lg = lane >> 2, lt = lane & 3;

    uint32_t aq[4][4];
    {
        int mr = m0 + warpm * 16;
#pragma unroll
        for (int s = 0; s < 4; s++) {
            int d0 = s * 16 + 2 * lt;
            aq[s][0] = *(const uint32_t*)(ql + (long)(mr + lg) * DHD + d0);
            aq[s][1] = *(const uint32_t*)(ql + (long)(mr + 8 + lg) * DHD + d0);
            aq[s][2] = *(const uint32_t*)(ql + (long)(mr + lg) * DHD + d0 + 8);
            aq[s][3] = *(const uint32_t*)(ql + (long)(mr + 8 + lg) * DHD + d0 + 8);
        }
    }

    float oacc[2][4];
#pragma unroll
    for (int nt = 0; nt < 2; nt++)
#pragma unroll
        for (int i = 0; i < 4; i++) oacc[nt][i] = 0.f;
    float mprev[2] = {-1e30f, -1e30f};
    float lsum[2]  = {0.f, 0.f};

    uint4 kpre[4];
    uint2 vpa[4], vpb[4];
#pragma unroll
    for (int j = 0; j < 4; j++) {
        int e = tid + j * 256;
        { int tok = e >> 3, g = e & 7;
          kpre[j] = *(const uint4*)(kg + (long)tok * DHD + 8 * g); }
        { int kpt = e >> 4, d4 = (e & 15) << 2;
          vpa[j] = *(const uint2*)(vg + (long)(2 * kpt) * DHD + d4);
          vpb[j] = *(const uint2*)(vg + (long)(2 * kpt + 1) * DHD + d4); }
    }

    for (int ch = 0; ch < NCH2; ch++) {
        __syncthreads();
#pragma unroll
        for (int j = 0; j < 4; j++) {
            int e = tid + j * 256;
            { int tok = e >> 3, g = e & 7;
              *(uint4*)&Ks[tok * 32 + 4 * (g ^ (tok & 7))] = kpre[j]; }
            { int kpt = e >> 4, d4 = (e & 15) << 2;
              uint4 w;
              w.x = prmtb(vpa[j].x, vpb[j].x, 0x5410);
              w.y = prmtb(vpa[j].x, vpb[j].x, 0x7632);
              w.z = prmtb(vpa[j].y, vpb[j].y, 0x5410);
              w.w = prmtb(vpa[j].y, vpb[j].y, 0x7632);
              *(uint4*)&Vs[kpt * 64 + (d4 ^ ((kpt & 3) << 3))] = w; }
        }
        if (ch + 1 < NCH2) {
            const __half* kc = kg + (long)(ch + 1) * SN2 * DHD;
            const __half* vc = vg + (long)(ch + 1) * SN2 * DHD;
#pragma unroll
            for (int j = 0; j < 4; j++) {
                int e = tid + j * 256;
                { int tok = e >> 3, g = e & 7;
                  kpre[j] = *(const uint4*)(kc + (long)tok * DHD + 8 * g); }
                { int kpt = e >> 4, d4 = (e & 15) << 2;
                  vpa[j] = *(const uint2*)(vc + (long)(2 * kpt) * DHD + d4);
                  vpb[j] = *(const uint2*)(vc + (long)(2 * kpt + 1) * DHD + d4); }
            }
        }
        __syncthreads();

        float sacc[4][4];
#pragma unroll
        for (int nt = 0; nt < 4; nt++)
#pragma unroll
            for (int i = 0; i < 4; i++) sacc[nt][i] = 0.f;
#pragma unroll
        for (int s = 0; s < 4; s++) {
            uint32_t bf[4][2];
#pragma unroll
            for (int nt = 0; nt < 4; nt++) {
                int c = warpn * 32 + nt * 8 + lg;
                bf[nt][0] = Ks[c * 32 + lt + 4 * ((2 * s) ^ (c & 7))];
                bf[nt][1] = Ks[c * 32 + lt + 4 * ((2 * s + 1) ^ (c & 7))];
            }
#pragma unroll
            for (int nt = 0; nt < 4; nt++)
                mma_f16(sacc[nt], aq[s], bf[nt]);
        }

#pragma unroll
        for (int half_ = 0; half_ < 2; half_++) {
            float mx = -1e30f;
#pragma unroll
            for (int nt = 0; nt < 4; nt++) {
                mx = fmaxf(mx, sacc[nt][half_ * 2]);
                mx = fmaxf(mx, sacc[nt][half_ * 2 + 1]);
            }
            mx = fmaxf(mx, __shfl_xor_sync(~0u, mx, 1));
            mx = fmaxf(mx, __shfl_xor_sync(~0u, mx, 2));
            if (lt == 0) redm[(warpm * 16 + half_ * 8 + lg) * 4 + warpn] = mx;
        }
        __syncthreads();

        float scale[2];
#pragma unroll
        for (int half_ = 0; half_ < 2; half_++) {
            int row = warpm * 16 + half_ * 8 + lg;
            float mch = fmaxf(fmaxf(redm[row * 4 + 0], redm[row * 4 + 1]),
                              fmaxf(redm[row * 4 + 2], redm[row * 4 + 3]));
            float mnew = fmaxf(mprev[half_], mch);
            scale[half_] = __expf(mprev[half_] - mnew);
            mprev[half_] = mnew;
            float s = 0.f;
#pragma unroll
            for (int nt = 0; nt < 4; nt++) {
                float e0 = __expf(sacc[nt][half_ * 2]     - mnew);
                float e1 = __expf(sacc[nt][half_ * 2 + 1] - mnew);
                sacc[nt][half_ * 2]     = e0;
                sacc[nt][half_ * 2 + 1] = e1;
                s += e0 + e1;
            }
            s += __shfl_xor_sync(~0u, s, 1);
            s += __shfl_xor_sync(~0u, s, 2);
            if (lt == 0) reds[row * 4 + warpn] = s;
#pragma unroll
            for (int nt = 0; nt < 4; nt++) {
                int kp = warpn * 16 + nt * 4 + lt;
                Ps[row * 64 + (kp ^ ((row & 7) << 2))] =
                    h2pack(sacc[nt][half_ * 2], sacc[nt][half_ * 2 + 1]);
            }
        }
        __syncthreads();

#pragma unroll
        for (int half_ = 0; half_ < 2; half_++) {
            int row = warpm * 16 + half_ * 8 + lg;
            lsum[half_] = lsum[half_] * scale[half_]
                        + reds[row * 4 + 0] + reds[row * 4 + 1]
                        + reds[row * 4 + 2] + reds[row * 4 + 3];
        }
#pragma unroll
        for (int nt = 0; nt < 2; nt++) {
            oacc[nt][0] *= scale[0]; oacc[nt][1] *= scale[0];
            oacc[nt][2] *= scale[1]; oacc[nt][3] *= scale[1];
        }

#pragma unroll
        for (int s = 0; s < 8; s++) {
            const int kp0 = s * 8;
            int mr = warpm * 16 + lg;
            uint32_t af[4];
            af[0] = Ps[mr * 64 + ((kp0 + lt) ^ ((mr & 7) << 2))];
            af[1] = Ps[(mr + 8) * 64 + ((kp0 + lt) ^ (((mr + 8) & 7) << 2))];
            af[2] = Ps[mr * 64 + ((kp0 + lt + 4) ^ ((mr & 7) << 2))];
            af[3] = Ps[(mr + 8) * 64 + ((kp0 + lt + 4) ^ (((mr + 8) & 7) << 2))];
            uint32_t bf[2][2];
#pragma unroll
            for (int nt = 0; nt < 2; nt++) {
                int d = warpn * 16 + nt * 8 + lg;
                bf[nt][0] = Vs[(kp0 + lt) * 64 + (d ^ (lt << 3))];
                bf[nt][1] = Vs[(kp0 + lt + 4) * 64 + (d ^ (lt << 3))];
            }
#pragma unroll
            for (int nt = 0; nt < 2; nt++)
                mma_f16(oacc[nt], af, bf[nt]);
        }
    }

    __half* outb = h_a3vT + (long)bh * DHD * MM;
#pragma unroll
    for (int half_ = 0; half_ < 2; half_++) {
        float inv = 1.f / lsum[half_];
        int r = m0 + warpm * 16 + half_ * 8 + lg;
#pragma unroll
        for (int nt = 0; nt < 2; nt++) {
            int d = warpn * 16 + nt * 8 + 2 * lt;
            outb[(long)d * MM + r]       = __float2half(oacc[nt][half_ * 2] * inv);
            outb[(long)(d + 1) * MM + r] = __float2half(oacc[nt][half_ * 2 + 1] * inv);
        }
    }
}

// ---------------- fused LayerNorm + weight conversion + colmax reset -----------
__global__ __launch_bounds__(256) void prep_kernel(
    const float* __restrict__ x, const float* __restrict__ w, const float* __restrict__ b,
    const float* __restrict__ wq, const float* __restrict__ wo)
{
    if (blockIdx.x == 0 && threadIdx.x == 0) g_colmax = 0.f;
    if (blockIdx.x < BB * NN) {
        long row = blockIdx.x;
        const float* xr = x + row * DD;
        int t = threadIdx.x;
        float v0 = xr[t], v1 = xr[t + 256];
        __shared__ float red[32];

        float s = v0 + v1;
        for (int o = 16; o > 0; o >>= 1) s += __shfl_xor_sync(~0u, s, o);
        if ((t & 31) == 0) red[t >> 5] = s;
        __syncthreads();
        if (t < 32) {
            float ss = (t < 8) ? red[t] : 0.f;
            for (int o = 4; o > 0; o >>= 1) ss += __shfl_xor_sync(~0u, ss, o);
            if (t == 0) red[0] = ss;
        }
        __syncthreads();
        float mu = red[0] * (1.f / DD);
        __syncthreads();

        float d0 = v0 - mu, d1 = v1 - mu;
        float q = d0 * d0 + d1 * d1;
        for (int o = 16; o > 0; o >>= 1) q += __shfl_xor_sync(~0u, q, o);
        if ((t & 31) == 0) red[t >> 5] = q;
        __syncthreads();
        if (t < 32) {
            float ss = (t < 8) ? red[t] : 0.f;
            for (int o = 4; o > 0; o >>= 1) ss += __shfl_xor_sync(~0u, ss, o);
            if (t == 0) red[0] = ss;
        }
        __syncthreads();
        float inv = rsqrtf(red[0] * (1.f / DD) + 1e-5f);
        h_xn[row * DD + t]       = __float2half(d0 * inv * w[t]       + b[t]);
        h_xn[row * DD + t + 256] = __float2half(d1 * inv * w[t + 256] + b[t + 256]);
    } else {
        int i = (blockIdx.x - BB * NN) * 256 + threadIdx.x;   // 3*DD*DD
        {
            int n = i / DD, k2 = i % DD;
            h_wqkvT[i] = __float2half(wq[(long)k2 * (3 * DD) + n]);
        }
        if (i < DD * DD) {
            int n = i / DD, k2 = i % DD;
            h_woutT[i] = __float2half(wo[(long)k2 * DD + n]);
        }
    }
}

// ---------------- landmarks (one half2 per thread, 1024 blocks) ----------------
__global__ void landmarks()
{
    long i = (long)blockIdx.x * 256 + threadIdx.x;    // BH*MM*32 d-pairs
    int dp = i & 31; long r = i >> 5;
    int m = r % MM;  int bh = r / MM;
    long base = ((long)bh * NN + m * LLm) * DHD + dp * 2;
    float sq0 = 0.f, sq1 = 0.f, sk0 = 0.f, sk1 = 0.f;
#pragma unroll
    for (int u = 0; u < LLm; u++) {
        float2 fq = __half22float2(*(const __half2*)(h_q + base + u * DHD));
        float2 fk = __half22float2(*(const __half2*)(h_k + base + u * DHD));
        sq0 += fq.x; sq1 += fq.y;
        sk0 += fk.x; sk1 += fk.y;
    }
    long out = ((long)bh * MM + m) * DHD + dp * 2;
    *(uint32_t*)(h_ql + out) = h2pack(sq0 * (1.f / LLm), sq1 * (1.f / LLm));
    *(uint32_t*)(h_kl + out) = h2pack(sk0 * (1.f / LLm), sk1 * (1.f / LLm));
}

// ---------------- pinv colmax + zinit -------------------------------------------
__global__ __launch_bounds__(256) void colmax_kernel()
{
    int bh = blockIdx.x, j = threadIdx.x;
    const __half* a = h_a2 + (long)bh * MM * MM;
    float s = 0.f;
    for (int i = 0; i < MM; i++) s += __half2float(a[i * MM + j]);
    __shared__ float red[32];
    float m = s;
    for (int o = 16; o > 0; o >>= 1) m = fmaxf(m, __shfl_xor_sync(~0u, m, o));
    if ((j & 31) == 0) red[j >> 5] = m;
    __syncthreads();
    if (j < 32) {
        float m2 = (j < 8) ? red[j] : -1e30f;
        for (int o = 4; o > 0; o >>= 1) m2 = fmaxf(m2, __shfl_xor_sync(~0u, m2, o));
        if (j == 0) atomicMax((int*)&g_colmax, __float_as_int(m2));
    }
}

__global__ void zinit()
{
    long i = (long)blockIdx.x * 256 + threadIdx.x;
    int col = i % MM; long r = i / MM;
    int row = r % MM; int bh = r / MM;
    float inv = 1.f / g_colmax;
    h_zT[i] = __float2half(__half2float(h_a2[i]) * inv);
    h_z [i] = __float2half(__half2float(h_a2[((long)bh * MM + col) * MM + row]) * inv);
}

// =============================================================================
// att_conv: att = reshape(o) + depthwise_conv(v). smem sliding-window version.
// Block = 128 tokens x one (b,h). V tokens [n0-16, n0+144) staged in smem
// [dp][tok] with 161 padding (conflict-free). Each thread: 16 consecutive
// tokens x 1 d-pair, diagonal s=t+j walk -> 48 smem loads per thread.
// Tap order (j ascending for fixed t) matches previous version bit-for-bit.
// =============================================================================
__global__ __launch_bounds__(256, 2) void att_conv(const float* __restrict__ rw)
{
    __shared__ uint32_t Vt[32 * 161];
    __shared__ float ws[KC];

    const int bh = blockIdx.x >> 5;
    const int n0 = (blockIdx.x & 31) * 128;
    const int b = bh / HH, h = bh % HH;
    const int tid = threadIdx.x;

    const __half* vb = h_v + (long)bh * NN * DHD;

#pragma unroll
    for (int k = 0; k < 20; k++) {
        int i = tid + k * 256;
        int tl = i >> 5, dp = i & 31;
        int tok = n0 - 16 + tl;
        uint32_t val = 0;
        if (tok >= 0 && tok < NN)
            val = *(const uint32_t*)(vb + (long)tok * DHD + dp * 2);
        Vt[dp * 161 + tl] = val;
    }
    if (tid < KC) ws[tid] = rw[h * KC + tid];
    __syncthreads();

    const int tg = tid >> 5, dp = tid & 31;
    const int nl0 = tg * 16;

    float acc[32];
    const __half* ob = h_o + (long)bh * NN * DHD;
#pragma unroll
    for (int t = 0; t < 16; t++) {
        uint32_t ov = *(const uint32_t*)(ob + (long)(n0 + nl0 + t) * DHD + dp * 2);
        float2 f = __half22float2(*(const __half2*)&ov);
        acc[2 * t] = f.x; acc[2 * t + 1] = f.y;
    }
#pragma unroll
    for (int s = 0; s < 48; s++) {
        float2 v2 = __half22float2(*(const __half2*)&Vt[dp * 161 + nl0 + s]);
        const int tlo = (s - 32 > 0) ? s - 32 : 0;
        const int thi = (s < 15) ? s : 15;
#pragma unroll
        for (int t = tlo; t <= thi; t++) {
            float w = ws[s - t];
            acc[2 * t]     += w * v2.x;
            acc[2 * t + 1] += w * v2.y;
        }
    }
    __half* attb = h_att + ((long)(b * NN + n0 + nl0)) * DD + h * DHD + dp * 2;
#pragma unroll
    for (int t = 0; t < 16; t++) {
        *(uint32_t*)(attb + (long)t * DD) = h2pack(acc[2 * t], acc[2 * t + 1]);
    }
}

// ---------------- host orchestration -------------------------------------------
extern "C" void kernel_launch(void* const* d_in, const int* in_sizes, int n_in,
                              void* d_out, int out_size)
{
    const float* x      = (const float*)d_in[0];
    const float* norm_w = (const float*)d_in[1];
    const float* norm_b = (const float*)d_in[2];
    const float* w_qkv  = (const float*)d_in[3];
    const float* w_out  = (const float*)d_in[4];
    const float* b_out  = (const float*)d_in[5];
    const float* res_w  = (const float*)d_in[6];
    float* y = (float*)d_out;

    __half *p_xn, *p_wqkvT, *p_woutT, *p_q, *p_k, *p_v, *p_ql, *p_kl;
    __half *p_a2, *p_z, *p_zT, *p_z2, *p_z2T, *p_xz, *p_t1T, *p_t2T, *p_a3vT, *p_WT, *p_att;
    cudaGetSymbolAddress((void**)&p_xn,   h_xn);
    cudaGetSymbolAddress((void**)&p_wqkvT,h_wqkvT);
    cudaGetSymbolAddress((void**)&p_woutT,h_woutT);
    cudaGetSymbolAddress((void**)&p_q,    h_q);
    cudaGetSymbolAddress((void**)&p_k,    h_k);
    cudaGetSymbolAddress((void**)&p_v,    h_v);
    cudaGetSymbolAddress((void**)&p_ql,   h_ql);
    cudaGetSymbolAddress((void**)&p_kl,   h_kl);
    cudaGetSymbolAddress((void**)&p_a2,   h_a2);
    cudaGetSymbolAddress((void**)&p_z,    h_z);
    cudaGetSymbolAddress((void**)&p_zT,   h_zT);
    cudaGetSymbolAddress((void**)&p_z2,   h_z2);
    cudaGetSymbolAddress((void**)&p_z2T,  h_z2T);
    cudaGetSymbolAddress((void**)&p_xz,   h_xz);
    cudaGetSymbolAddress((void**)&p_t1T,  h_t1T);
    cudaGetSymbolAddress((void**)&p_t2T,  h_t2T);
    cudaGetSymbolAddress((void**)&p_a3vT, h_a3vT);
    cudaGetSymbolAddress((void**)&p_WT,   h_WT);
    cudaGetSymbolAddress((void**)&p_att,  h_att);

    const long MM2 = (long)MM * MM;
    void* nul = nullptr;

    // 1. LayerNorm + weight conversion + colmax reset (single launch)
    prep_kernel<<<BB * NN + (3 * DD * DD) / 256, 256>>>(
        x, norm_w, norm_b, w_qkv, w_out);
    // 2. qkv GEMM with fused split
    gemm_h<128, 1><<<dim3((3 * DD) / 128, (BB * NN) / 128, 1), 256>>>(
        p_xn, p_wqkvT, p_q, p_k, p_v,
        BB * NN, 3 * DD, DD, 0, 0, 0, 1.f, 0.f);
    // 3. landmarks
    landmarks<<<(BH * MM * 32) / 256, 256>>>();
    // 4. a2 = softmax(ql @ kl^T)
    sim_softmax_h<<<dim3(MM / 64, 1, BH), 256>>>(
        p_ql, p_kl, p_a2, (long)MM * DHD, (long)MM * DHD, MM2);
    // 5. pinv init
    colmax_kernel<<<BH, 256>>>();
    zinit<<<(int)((long)BH * MM * MM / 256), 256>>>();
    // 6. Newton-Schulz
    __half *zin = p_z, *zinT = p_zT, *zout = p_z2, *zoutT = p_z2T;
    for (int it = 0; it < NITER; it++) {
        gemm_h<64, 3><<<dim3(MM / 64, MM / 128, BH), 256>>>(
            p_a2, zinT, p_xz, nul, p_t1T, MM, MM, MM, MM2, MM2, MM2, 1.f, 7.f);
        gemm_h<64, 3><<<dim3(MM / 64, MM / 128, BH), 256>>>(
            p_xz, p_t1T, nul, nul, p_t2T, MM, MM, MM, MM2, MM2, MM2, 1.f, 15.f);
        gemm_h<64, 3><<<dim3(MM / 64, MM / 128, BH), 256>>>(
            p_xz, p_t2T, nul, nul, p_t1T, MM, MM, MM, MM2, MM2, MM2, 1.f, 13.f);
        gemm_h<64, 3><<<dim3(MM / 64, MM / 128, BH), 256>>>(
            zin, p_t1T, zout, zoutT, nul, MM, MM, MM, MM2, MM2, MM2, 0.25f, 0.f);
        __half* t;
        t = zin;  zin  = zout;  zout  = t;
        t = zinT; zinT = zoutT; zoutT = t;
    }
    // 7. a3vT = (softmax(ql @ k^T) @ v)^T  (flash)
    a3v_flash_h<<<dim3(MM / 32, 1, BH), 256>>>();
    // 8. WT = (z @ a3v)^T
    gemm_h<64, 3><<<dim3(1, MM / 128, BH), 256>>>(
        zin, p_a3vT, nul, p_WT, nul, MM, DHD, MM,
        MM2, (long)DHD * MM, (long)DHD * MM, 1.f, 0.f);
    // 9. o = softmax(q @ kl^T) @ W  (fully fused)
    sim_out_h<<<dim3(NN / 64, 1, BH), 256>>>();
    // 10. att = reshape(o) + conv(v)  (smem sliding-window)
    att_conv<<<BH * (NN / 128), 256>>>(res_w);
    // 11. y = att @ w_out + x + b_out
    gemm_h<128, 2><<<dim3(DD / 128, (BB * NN) / 128, 1), 256>>>(
        p_att, p_woutT, y, (void*)x, (void*)b_out,
        BB * NN, DD, DD, 0, 0, 0, 1.f, 0.f);
}

// round 17
// speedup vs baseline: 1.0729x; 1.0218x over previous
#include <cuda_runtime.h>
#include <cuda_fp16.h>
#include <cstdint>

#define BB 4
#define NN 4096
#define DD 512
#define HH 8
#define DHD 64
#define MM 256
#define LLm 16
#define NITER 6
#define KC 33
#define BH (BB*HH)
#define SN2 128
#define NCH2 (NN/SN2)

// ---------------- scratch -------------------------------------------------------
__device__ __align__(16) __half h_xn   [BB*NN*DD];
__device__ __align__(16) __half h_wqkvT[3*DD*DD];
__device__ __align__(16) __half h_woutT[DD*DD];
__device__ __align__(16) __half h_q  [BH*NN*DHD];
__device__ __align__(16) __half h_k  [BH*NN*DHD];
__device__ __align__(16) __half h_v  [BH*NN*DHD];
__device__ __align__(16) __half h_o  [BH*NN*DHD];
__device__ __align__(16) __half h_ql [BH*MM*DHD];
__device__ __align__(16) __half h_kl [BH*MM*DHD];
__device__ __align__(16) __half h_a2 [BH*MM*MM];
__device__ __align__(16) __half h_z  [BH*MM*MM];
__device__ __align__(16) __half h_zT [BH*MM*MM];
__device__ __align__(16) __half h_z2 [BH*MM*MM];
__device__ __align__(16) __half h_z2T[BH*MM*MM];
__device__ __align__(16) __half h_xz [BH*MM*MM];
__device__ __align__(16) __half h_t1T[BH*MM*MM];
__device__ __align__(16) __half h_t2T[BH*MM*MM];
__device__ __align__(16) __half h_a3vT[BH*DHD*MM];    // [d][m]
__device__ __align__(16) __half h_WT [BH*DHD*MM];     // [d][m]
__device__ __align__(16) __half h_att[BB*NN*DD];
__device__ float g_colmax;

// ---------------- helpers ------------------------------------------------------
__device__ __forceinline__ uint32_t h2pack(float a, float b) {
    __half2 h = __floats2half2_rn(a, b);
    return *reinterpret_cast<uint32_t*>(&h);
}
__device__ __forceinline__ uint32_t prmtb(uint32_t a, uint32_t b, uint32_t sel) {
    uint32_t d;
    asm("prmt.b32 %0, %1, %2, %3;" : "=r"(d) : "r"(a), "r"(b), "r"(sel));
    return d;
}
__device__ __forceinline__ void mma_f16(float* c, const uint32_t* a, const uint32_t* b) {
    asm volatile(
        "mma.sync.aligned.m16n8k16.row.col.f32.f16.f16.f32 "
        "{%0,%1,%2,%3}, {%4,%5,%6,%7}, {%8,%9}, {%0,%1,%2,%3};"
        : "+f"(c[0]), "+f"(c[1]), "+f"(c[2]), "+f"(c[3])
        : "r"(a[0]), "r"(a[1]), "r"(a[2]), "r"(a[3]), "r"(b[0]), "r"(b[1]));
}
__device__ __forceinline__ void ldsm4(uint32_t* r, uint32_t saddr) {
    asm volatile("ldmatrix.sync.aligned.m8n8.x4.shared.b16 {%0,%1,%2,%3}, [%4];"
        : "=r"(r[0]), "=r"(r[1]), "=r"(r[2]), "=r"(r[3]) : "r"(saddr));
}
__device__ __forceinline__ void ldsm2(uint32_t* r, uint32_t saddr) {
    asm volatile("ldmatrix.sync.aligned.m8n8.x2.shared.b16 {%0,%1}, [%2];"
        : "=r"(r[0]), "=r"(r[1]) : "r"(saddr));
}
__device__ __forceinline__ void cpa16(uint32_t dst, const void* src) {
    asm volatile("cp.async.cg.shared.global [%0], [%1], 16;" :: "r"(dst), "l"(src));
}
#define CP_COMMIT() asm volatile("cp.async.commit_group;")

// =============================================================================
// gemm_h: C = alpha * A @ B^T, A [M][K] half, B [N][K] half (both k-contig).
// BM=128, BN template, BK=32. 2-stage cp.async + LDSM.
// 8 warps 4m x 2n.
// MODE 0: p0 = float* C ; MODE 1: qkv split ; MODE 2: y = acc + x + bout
// MODE 3: p0 Cn(half normal), p1 CtRaw(half transp), p2 CtDiag(half transp).
//         Transposed outputs staged in smem, written back coalesced.
// =============================================================================
template<int BN, int MODE>
__global__ __launch_bounds__(256, 2) void gemm_h(
    const __half* __restrict__ Ag, const __half* __restrict__ Bg,
    void* __restrict__ p0, void* __restrict__ p1, void* __restrict__ p2,
    int Md, int Nd, int Kd, long sA, long sB, long sC,
    float alpha, float dg)
{
    constexpr int NT = BN / 16;
    constexpr int WN = BN / 2;
    constexpr int NBJ = BN / 64;

    __shared__ uint32_t SM[2 * 2048 + 2 * BN * 16];
    uint32_t* As = SM;                 // 2 stages x 2048
    uint32_t* Bs = SM + 4096;          // 2 stages x BN*16

    const __half* A = Ag + (long)blockIdx.z * sA;
    const __half* Bp = Bg + (long)blockIdx.z * sB;
    const int m0 = blockIdx.y * 128;
    const int n0 = blockIdx.x * BN;
    const int tid = threadIdx.x;
    const int wid = tid >> 5, lane = tid & 31;
    const int warpm = wid & 3, warpn = wid >> 2;
    const int lg = lane >> 2, lt = lane & 3;

    const uint32_t asmb = (uint32_t)__cvta_generic_to_shared(As);
    const uint32_t bsmb = (uint32_t)__cvta_generic_to_shared(Bs);

    const int t4  = lane >> 3;
    const int agh = t4 >> 1;
    int aoff[2], asw[2];
#pragma unroll
    for (int mt = 0; mt < 2; mt++) {
        int rr = warpm * 32 + mt * 16 + (t4 & 1) * 8 + (lane & 7);
        aoff[mt] = rr * 64;
        asw[mt]  = (rr >> 1) & 3;
    }
    const int btb = t4 & 1;
    int boff[NT], bsw[NT];
#pragma unroll
    for (int nt = 0; nt < NT; nt++) {
        int n = warpn * WN + nt * 8 + (lane & 7);
        boff[nt] = n * 64;
        bsw[nt]  = (n >> 1) & 3;
    }

    float acc[2][NT][4];
#pragma unroll
    for (int mt = 0; mt < 2; mt++)
#pragma unroll
        for (int nt = 0; nt < NT; nt++)
#pragma unroll
            for (int i = 0; i < 4; i++) acc[mt][nt][i] = 0.f;

    const int nk = Kd >> 5;

#define LOADT(kt, st) do {                                                      \
    const int k0_ = (kt) << 5;                                                  \
    _Pragma("unroll")                                                           \
    for (int j = 0; j < 2; j++) {                                               \
        int e = tid + j * 256;                                                  \
        int row = e >> 2, g = e & 3;                                            \
        uint32_t d = asmb + (uint32_t)(((st) * 2048 + row * 16 +                \
                     4 * (g ^ ((row >> 1) & 3))) << 2);                         \
        cpa16(d, A + (long)(m0 + row) * Kd + k0_ + 8 * g);                      \
    }                                                                           \
    _Pragma("unroll")                                                           \
    for (int j = 0; j < NBJ; j++) {                                             \
        int e = tid + j * 256;                                                  \
        int n = e >> 2, g = e & 3;                                              \
        uint32_t d = bsmb + (uint32_t)(((st) * (BN * 16) + n * 16 +             \
                     4 * (g ^ ((n >> 1) & 3))) << 2);                           \
        cpa16(d, Bp + (long)(n0 + n) * Kd + k0_ + 8 * g);                       \
    }                                                                           \
    CP_COMMIT();                                                                \
} while (0)

    LOADT(0, 0);

    for (int kt = 0; kt < nk; kt++) {
        const int st = kt & 1;
        if (kt + 1 < nk) {
            LOADT(kt + 1, st ^ 1);
            asm volatile("cp.async.wait_group 1;");
        } else {
            asm volatile("cp.async.wait_group 0;");
        }
        __syncthreads();

        const uint32_t a_base = asmb + (uint32_t)((st * 2048) << 2);
        const uint32_t b_base = bsmb + (uint32_t)((st * (BN * 16)) << 2);
#pragma unroll
        for (int s = 0; s < 2; s++) {
            uint32_t af[2][4], bf[NT][2];
#pragma unroll
            for (int mt = 0; mt < 2; mt++)
                ldsm4(af[mt], a_base + (uint32_t)((aoff[mt] +
                      ((((s << 1) | agh) ^ asw[mt]) << 4))));
#pragma unroll
            for (int nt = 0; nt < NT; nt++)
                ldsm2(bf[nt], b_base + (uint32_t)((boff[nt] +
                      ((((s << 1) | btb) ^ bsw[nt]) << 4))));
#pragma unroll
            for (int mt = 0; mt < 2; mt++)
#pragma unroll
                for (int nt = 0; nt < NT; nt++)
                    mma_f16(acc[mt][nt], af[mt], bf[nt]);
        }
        __syncthreads();
    }
#undef LOADT

    if (MODE == 0) {
        float* C = (float*)p0 + (long)blockIdx.z * sC;
#pragma unroll
        for (int mt = 0; mt < 2; mt++)
#pragma unroll
            for (int nt = 0; nt < NT; nt++) {
                int r = m0 + warpm * 32 + mt * 16 + lg;
                int c = n0 + warpn * WN + nt * 8 + 2 * lt;
                *(float2*)(C + (long)r * Nd + c) =
                    make_float2(acc[mt][nt][0] * alpha, acc[mt][nt][1] * alpha);
                *(float2*)(C + (long)(r + 8) * Nd + c) =
                    make_float2(acc[mt][nt][2] * alpha, acc[mt][nt][3] * alpha);
            }
    } else if (MODE == 1) {
        __half* qh = (__half*)p0; __half* kh = (__half*)p1; __half* vh = (__half*)p2;
#pragma unroll
        for (int mt = 0; mt < 2; mt++)
#pragma unroll
            for (int nt = 0; nt < NT; nt++) {
                int c = n0 + warpn * WN + nt * 8 + 2 * lt;
                int which = c >> 9, cc = c & 511;
                int h = cc >> 6, d = cc & 63;
                float sc = (which == 0) ? 0.125f : 1.f;
                __half* dsth = (which == 0) ? qh : (which == 1) ? kh : vh;
#pragma unroll
                for (int half_ = 0; half_ < 2; half_++) {
                    int m = m0 + warpm * 32 + mt * 16 + half_ * 8 + lg;
                    int b = m >> 12, n = m & 4095;
                    long dst = ((long)(b * HH + h) * NN + n) * DHD + d;
                    *(uint32_t*)(dsth + dst) = h2pack(acc[mt][nt][half_ * 2] * sc,
                                                      acc[mt][nt][half_ * 2 + 1] * sc);
                }
            }
    } else if (MODE == 2) {
        float* y = (float*)p0;
        const float* xp = (const float*)p1;
        const float* bp = (const float*)p2;
#pragma unroll
        for (int mt = 0; mt < 2; mt++)
#pragma unroll
            for (int nt = 0; nt < NT; nt++) {
                int r = m0 + warpm * 32 + mt * 16 + lg;
                int c = n0 + warpn * WN + nt * 8 + 2 * lt;
                float b0 = bp[c], b1 = bp[c + 1];
                float2 x0 = *(const float2*)(xp + (long)r * Nd + c);
                float2 x1 = *(const float2*)(xp + (long)(r + 8) * Nd + c);
                *(float2*)(y + (long)r * Nd + c) =
                    make_float2(acc[mt][nt][0] + x0.x + b0, acc[mt][nt][1] + x0.y + b1);
                *(float2*)(y + (long)(r + 8) * Nd + c) =
                    make_float2(acc[mt][nt][2] + x1.x + b0, acc[mt][nt][3] + x1.y + b1);
            }
    } else {
        __half* Cn = p0 ? (__half*)p0 + (long)blockIdx.z * sC : nullptr;
        __half* Ctr = p1 ? (__half*)p1 + (long)blockIdx.z * sC : nullptr;
        __half* Ctd = p2 ? (__half*)p2 + (long)blockIdx.z * sC : nullptr;
        if (Cn) {
#pragma unroll
            for (int mt = 0; mt < 2; mt++)
#pragma unroll
                for (int nt = 0; nt < NT; nt++) {
                    int r = m0 + warpm * 32 + mt * 16 + lg;
                    int c = n0 + warpn * WN + nt * 8 + 2 * lt;
                    *(uint32_t*)(Cn + (long)r * Nd + c) =
                        h2pack(acc[mt][nt][0] * alpha, acc[mt][nt][1] * alpha);
                    *(uint32_t*)(Cn + (long)(r + 8) * Nd + c) =
                        h2pack(acc[mt][nt][2] * alpha, acc[mt][nt][3] * alpha);
                }
        }
        if (Ctr || Ctd) {
            // stage transposed tile in smem: CT[c_local][r_local], stride 136 halves
            __half* CT = (__half*)SM;
#pragma unroll
            for (int mt = 0; mt < 2; mt++)
#pragma unroll
                for (int nt = 0; nt < NT; nt++) {
                    int rl = warpm * 32 + mt * 16 + lg;
                    int cl = warpn * WN + nt * 8 + 2 * lt;
                    int r = m0 + rl, c = n0 + cl;
                    float v00 = acc[mt][nt][0] * alpha;
                    float v01 = acc[mt][nt][1] * alpha;
                    float v10 = acc[mt][nt][2] * alpha;
                    float v11 = acc[mt][nt][3] * alpha;
                    if (Ctd) {
                        v00 = ((r == c)         ? dg : 0.f) - v00;
                        v01 = ((r == c + 1)     ? dg : 0.f) - v01;
                        v10 = ((r + 8 == c)     ? dg : 0.f) - v10;
                        v11 = ((r + 8 == c + 1) ? dg : 0.f) - v11;
                    }
                    CT[cl * 136 + rl]           = __float2half(v00);
                    CT[(cl + 1) * 136 + rl]     = __float2half(v01);
                    CT[cl * 136 + rl + 8]       = __float2half(v10);
                    CT[(cl + 1) * 136 + rl + 8] = __float2half(v11);
                }
            __syncthreads();
            __half* dstT = Ctr ? Ctr : Ctd;
#pragma unroll
            for (int k = 0; k < BN / 16; k++) {
                int e = tid + k * 256;
                int n = e >> 4, g = e & 15;
                *(uint4*)(dstT + (long)(n0 + n) * Md + m0 + 8 * g) =
                    *(const uint4*)(CT + n * 136 + 8 * g);
            }
        }
    }
}

// =============================================================================
// sim_softmax_h: Out(half) = softmax_row(A @ B^T)  (used for a2 only)
// =============================================================================
__global__ __launch_bounds__(256, 2) void sim_softmax_h(
    const __half* __restrict__ Ag, const __half* __restrict__ Bg,
    __half* __restrict__ Og, long sA, long sB, long sO)
{
    __shared__ uint32_t As[64 * 16];
    __shared__ uint32_t Bs[256 * 16];
    __shared__ float redm[64 * 4];
    __shared__ float reds[64 * 4];

    const __half* A = Ag + (long)blockIdx.z * sA;
    const __half* B = Bg + (long)blockIdx.z * sB;
    __half*       O = Og + (long)blockIdx.z * sO;
    const int m0 = blockIdx.x * 64;
    const int tid = threadIdx.x;
    const int wid = tid >> 5, lane = tid & 31;
    const int warpm = wid & 1, warpn = wid >> 1;
    const int lg = lane >> 2, lt = lane & 3;

    const uint32_t asmb = (uint32_t)__cvta_generic_to_shared(&As[0]);
    const uint32_t bsmb = (uint32_t)__cvta_generic_to_shared(&Bs[0]);

    const int t4  = lane >> 3;
    const int agh = t4 >> 1;
    int aoff[2], asw[2];
#pragma unroll
    for (int mt = 0; mt < 2; mt++) {
        int rr = warpm * 32 + mt * 16 + (t4 & 1) * 8 + (lane & 7);
        aoff[mt] = rr * 64;
        asw[mt]  = (rr >> 1) & 3;
    }
    const int btb = t4 & 1;
    int boff[8], bsw[8];
#pragma unroll
    for (int nt = 0; nt < 8; nt++) {
        int n = warpn * 64 + nt * 8 + (lane & 7);
        boff[nt] = n * 64;
        bsw[nt]  = (n >> 1) & 3;
    }

    float acc[2][8][4];
#pragma unroll
    for (int mt = 0; mt < 2; mt++)
#pragma unroll
        for (int nt = 0; nt < 8; nt++)
#pragma unroll
            for (int i = 0; i < 4; i++) acc[mt][nt][i] = 0.f;

#pragma unroll
    for (int kt = 0; kt < 2; kt++) {
        const int k0 = kt * 32;
        {
            int row = tid >> 2, g = tid & 3;
            uint4 va = *(const uint4*)(A + (long)(m0 + row) * DHD + k0 + 8 * g);
            *(uint4*)&As[row * 16 + 4 * (g ^ ((row >> 1) & 3))] = va;
        }
#pragma unroll
        for (int j = 0; j < 4; j++) {
            int e = tid + j * 256;
            int n = e >> 2, g = e & 3;
            uint4 vb = *(const uint4*)(B + (long)n * DHD + k0 + 8 * g);
            *(uint4*)&Bs[n * 16 + 4 * (g ^ ((n >> 1) & 3))] = vb;
        }
        __syncthreads();

#pragma unroll
        for (int s = 0; s < 2; s++) {
            uint32_t af[2][4], bf[8][2];
#pragma unroll
            for (int mt = 0; mt < 2; mt++)
                ldsm4(af[mt], asmb + (uint32_t)(aoff[mt] +
                      ((((s << 1) | agh) ^ asw[mt]) << 4)));
#pragma unroll
            for (int nt = 0; nt < 8; nt++)
                ldsm2(bf[nt], bsmb + (uint32_t)(boff[nt] +
                      ((((s << 1) | btb) ^ bsw[nt]) << 4)));
#pragma unroll
            for (int mt = 0; mt < 2; mt++)
#pragma unroll
                for (int nt = 0; nt < 8; nt++)
                    mma_f16(acc[mt][nt], af[mt], bf[nt]);
        }
        __syncthreads();
    }

#pragma unroll
    for (int mt = 0; mt < 2; mt++)
#pragma unroll
        for (int half_ = 0; half_ < 2; half_++) {
            float mx = -1e30f;
#pragma unroll
            for (int nt = 0; nt < 8; nt++) {
                mx = fmaxf(mx, acc[mt][nt][half_ * 2]);
                mx = fmaxf(mx, acc[mt][nt][half_ * 2 + 1]);
            }
            mx = fmaxf(mx, __shfl_xor_sync(~0u, mx, 1));
            mx = fmaxf(mx, __shfl_xor_sync(~0u, mx, 2));
            int rloc = warpm * 32 + mt * 16 + half_ * 8 + lg;
            if (lt == 0) redm[rloc * 4 + warpn] = mx;
        }
    __syncthreads();
#pragma unroll
    for (int mt = 0; mt < 2; mt++)
#pragma unroll
        for (int half_ = 0; half_ < 2; half_++) {
            int rloc = warpm * 32 + mt * 16 + half_ * 8 + lg;
            float m4 = fmaxf(fmaxf(redm[rloc * 4 + 0], redm[rloc * 4 + 1]),
                             fmaxf(redm[rloc * 4 + 2], redm[rloc * 4 + 3]));
            float s = 0.f;
#pragma unroll
            for (int nt = 0; nt < 8; nt++) {
                float e0 = __expf(acc[mt][nt][half_ * 2]     - m4);
                float e1 = __expf(acc[mt][nt][half_ * 2 + 1] - m4);
                acc[mt][nt][half_ * 2]     = e0;
                acc[mt][nt][half_ * 2 + 1] = e1;
                s += e0 + e1;
            }
            s += __shfl_xor_sync(~0u, s, 1);
            s += __shfl_xor_sync(~0u, s, 2);
            if (lt == 0) reds[rloc * 4 + warpn] = s;
        }
    __syncthreads();
#pragma unroll
    for (int mt = 0; mt < 2; mt++)
#pragma unroll
        for (int half_ = 0; half_ < 2; half_++) {
            int rloc = warpm * 32 + mt * 16 + half_ * 8 + lg;
            float tot = reds[rloc * 4 + 0] + reds[rloc * 4 + 1]
                      + reds[rloc * 4 + 2] + reds[rloc * 4 + 3];
            float inv = 1.f / tot;
            int r = m0 + rloc;
#pragma unroll
            for (int nt = 0; nt < 8; nt++) {
                int c = warpn * 64 + nt * 8 + 2 * lt;
                *(uint32_t*)(O + (long)r * MM + c) =
                    h2pack(acc[mt][nt][half_ * 2] * inv, acc[mt][nt][half_ * 2 + 1] * inv);
            }
        }
}

// =============================================================================
// sim_out_h: o = softmax_row(q @ kl^T) @ W, fully fused (a1 never materialized).
// =============================================================================
__global__ __launch_bounds__(256, 2) void sim_out_h()
{
    __shared__ uint32_t S[8192];
    __shared__ float redm[64 * 4];
    __shared__ float reds[64 * 4];

    const int bh = blockIdx.z;
    const __half* A = h_q  + (long)bh * NN * DHD;
    const __half* B = h_kl + (long)bh * MM * DHD;
    const __half* WTb = h_WT + (long)bh * DHD * MM;
    const int m0 = blockIdx.x * 64;
    const int tid = threadIdx.x;
    const int wid = tid >> 5, lane = tid & 31;
    const int warpm = wid & 1, warpn = wid >> 1;
    const int lg = lane >> 2, lt = lane & 3;

    uint32_t* As = S;
    uint32_t* Bs = S + 1024;
    const uint32_t asmb = (uint32_t)__cvta_generic_to_shared(As);
    const uint32_t bsmb = (uint32_t)__cvta_generic_to_shared(Bs);

    const int t4  = lane >> 3;
    const int agh = t4 >> 1;
    int aoff[2], asw[2];
#pragma unroll
    for (int mt = 0; mt < 2; mt++) {
        int rr = warpm * 32 + mt * 16 + (t4 & 1) * 8 + (lane & 7);
        aoff[mt] = rr * 64;
        asw[mt]  = (rr >> 1) & 3;
    }
    const int btb = t4 & 1;
    int boff[8], bsw[8];
#pragma unroll
    for (int nt = 0; nt < 8; nt++) {
        int n = warpn * 64 + nt * 8 + (lane & 7);
        boff[nt] = n * 64;
        bsw[nt]  = (n >> 1) & 3;
    }

    float acc[2][8][4];
#pragma unroll
    for (int mt = 0; mt < 2; mt++)
#pragma unroll
        for (int nt = 0; nt < 8; nt++)
#pragma unroll
            for (int i = 0; i < 4; i++) acc[mt][nt][i] = 0.f;

#pragma unroll
    for (int kt = 0; kt < 2; kt++) {
        const int k0 = kt * 32;
        {
            int row = tid >> 2, g = tid & 3;
            uint4 va = *(const uint4*)(A + (long)(m0 + row) * DHD + k0 + 8 * g);
            *(uint4*)&As[row * 16 + 4 * (g ^ ((row >> 1) & 3))] = va;
        }
#pragma unroll
        for (int j = 0; j < 4; j++) {
            int e = tid + j * 256;
            int n = e >> 2, g = e & 3;
            uint4 vb = *(const uint4*)(B + (long)n * DHD + k0 + 8 * g);
            *(uint4*)&Bs[n * 16 + 4 * (g ^ ((n >> 1) & 3))] = vb;
        }
        __syncthreads();

#pragma unroll
        for (int s = 0; s < 2; s++) {
            uint32_t af[2][4], bf[8][2];
#pragma unroll
            for (int mt = 0; mt < 2; mt++)
                ldsm4(af[mt], asmb + (uint32_t)(aoff[mt] +
                      ((((s << 1) | agh) ^ asw[mt]) << 4)));
#pragma unroll
            for (int nt = 0; nt < 8; nt++)
                ldsm2(bf[nt], bsmb + (uint32_t)(boff[nt] +
                      ((((s << 1) | btb) ^ bsw[nt]) << 4)));
#pragma unroll
            for (int mt = 0; mt < 2; mt++)
#pragma unroll
                for (int nt = 0; nt < 8; nt++)
                    mma_f16(acc[mt][nt], af[mt], bf[nt]);
        }
        __syncthreads();
    }

#pragma unroll
    for (int mt = 0; mt < 2; mt++)
#pragma unroll
        for (int half_ = 0; half_ < 2; half_++) {
            float mx = -1e30f;
#pragma unroll
            for (int nt = 0; nt < 8; nt++) {
                mx = fmaxf(mx, acc[mt][nt][half_ * 2]);
                mx = fmaxf(mx, acc[mt][nt][half_ * 2 + 1]);
            }
            mx = fmaxf(mx, __shfl_xor_sync(~0u, mx, 1));
            mx = fmaxf(mx, __shfl_xor_sync(~0u, mx, 2));
            int rloc = warpm * 32 + mt * 16 + half_ * 8 + lg;
            if (lt == 0) redm[rloc * 4 + warpn] = mx;
        }
    __syncthreads();
#pragma unroll
    for (int mt = 0; mt < 2; mt++)
#pragma unroll
        for (int half_ = 0; half_ < 2; half_++) {
            int rloc = warpm * 32 + mt * 16 + half_ * 8 + lg;
            float m4 = fmaxf(fmaxf(redm[rloc * 4 + 0], redm[rloc * 4 + 1]),
                             fmaxf(redm[rloc * 4 + 2], redm[rloc * 4 + 3]));
            float s = 0.f;
#pragma unroll
            for (int nt = 0; nt < 8; nt++) {
                float e0 = __expf(acc[mt][nt][half_ * 2]     - m4);
                float e1 = __expf(acc[mt][nt][half_ * 2 + 1] - m4);
                acc[mt][nt][half_ * 2]     = e0;
                acc[mt][nt][half_ * 2 + 1] = e1;
                s += e0 + e1;
            }
            s += __shfl_xor_sync(~0u, s, 1);
            s += __shfl_xor_sync(~0u, s, 2);
            if (lt == 0) reds[rloc * 4 + warpn] = s;
        }
    __syncthreads();
#pragma unroll
    for (int mt = 0; mt < 2; mt++)
#pragma unroll
        for (int half_ = 0; half_ < 2; half_++) {
            int rloc = warpm * 32 + mt * 16 + half_ * 8 + lg;
            float tot = reds[rloc * 4 + 0] + reds[rloc * 4 + 1]
                      + reds[rloc * 4 + 2] + reds[rloc * 4 + 3];
            float inv = 1.f / tot;
#pragma unroll
            for (int nt = 0; nt < 8; nt++) {
                int kp = warpn * 32 + nt * 4 + lt;
                S[rloc * 128 + (kp ^ ((rloc & 7) << 2))] =
                    h2pack(acc[mt][nt][half_ * 2] * inv, acc[mt][nt][half_ * 2 + 1] * inv);
            }
        }
    __syncthreads();

    float oacc[2][2][4];
#pragma unroll
    for (int mt = 0; mt < 2; mt++)
#pragma unroll
        for (int nt = 0; nt < 2; nt++)
#pragma unroll
            for (int i = 0; i < 4; i++) oacc[mt][nt][i] = 0.f;

#pragma unroll
    for (int s = 0; s < 16; s++) {
        const int kp0 = s * 8;
        uint32_t af[2][4], bf[2][2];
#pragma unroll
        for (int mt = 0; mt < 2; mt++) {
            int mr = warpm * 32 + mt * 16 + lg;
            af[mt][0] = S[mr * 128 + ((kp0 + lt) ^ ((mr & 7) << 2))];
            af[mt][1] = S[(mr + 8) * 128 + ((kp0 + lt) ^ (((mr + 8) & 7) << 2))];
            af[mt][2] = S[mr * 128 + ((kp0 + lt + 4) ^ ((mr & 7) << 2))];
            af[mt][3] = S[(mr + 8) * 128 + ((kp0 + lt + 4) ^ (((mr + 8) & 7) << 2))];
        }
#pragma unroll
        for (int nt = 0; nt < 2; nt++) {
            int d = warpn * 16 + nt * 8 + lg;
            bf[nt][0] = *(const uint32_t*)(WTb + (long)d * MM + s * 16 + 2 * lt);
            bf[nt][1] = *(const uint32_t*)(WTb + (long)d * MM + s * 16 + 8 + 2 * lt);
        }
#pragma unroll
        for (int mt = 0; mt < 2; mt++)
#pragma unroll
            for (int nt = 0; nt < 2; nt++)
                mma_f16(oacc[mt][nt], af[mt], bf[nt]);
    }

    __half* ob = h_o + (long)bh * NN * DHD;
#pragma unroll
    for (int mt = 0; mt < 2; mt++)
#pragma unroll
        for (int half_ = 0; half_ < 2; half_++) {
            int r = m0 + warpm * 32 + mt * 16 + half_ * 8 + lg;
#pragma unroll
            for (int nt = 0; nt < 2; nt++) {
                int d = warpn * 16 + nt * 8 + 2 * lt;
                *(uint32_t*)(ob + (long)r * DHD + d) =
                    h2pack(oacc[mt][nt][half_ * 2], oacc[mt][nt][half_ * 2 + 1]);
            }
        }
}

// =============================================================================
// a3v_flash_h: a3vT = (softmax_row(ql @ k^T) @ v)^T, SN2=128 chunks.
// =============================================================================
__global__ __launch_bounds__(256, 2) void a3v_flash_h()
{
    __shared__ uint32_t Ks[128 * 32];
    __shared__ uint32_t Vs[64 * 64];
    __shared__ uint32_t Ps[32 * 64];
    __shared__ float redm[32 * 4];
    __shared__ float reds[32 * 4];

    const int bh = blockIdx.z;
    const int m0 = blockIdx.x * 32;
    const __half* ql = h_ql + (long)bh * MM * DHD;
    const __half* kg = h_k  + (long)bh * NN * DHD;
    const __half* vg = h_v  + (long)bh * NN * DHD;

    const int tid = threadIdx.x;
    const int wid = tid >> 5, lane = tid & 31;
    const int warpm = wid & 1, warpn = wid >> 1;
    const int lg = lane >> 2, lt = lane & 3;

    uint32_t aq[4][4];
    {
        int mr = m0 + warpm * 16;
#pragma unroll
        for (int s = 0; s < 4; s++) {
            int d0 = s * 16 + 2 * lt;
            aq[s][0] = *(const uint32_t*)(ql + (long)(mr + lg) * DHD + d0);
            aq[s][1] = *(const uint32_t*)(ql + (long)(mr + 8 + lg) * DHD + d0);
            aq[s][2] = *(const uint32_t*)(ql + (long)(mr + lg) * DHD + d0 + 8);
            aq[s][3] = *(const uint32_t*)(ql + (long)(mr + 8 + lg) * DHD + d0 + 8);
        }
    }

    float oacc[2][4];
#pragma unroll
    for (int nt = 0; nt < 2; nt++)
#pragma unroll
        for (int i = 0; i < 4; i++) oacc[nt][i] = 0.f;
    float mprev[2] = {-1e30f, -1e30f};
    float lsum[2]  = {0.f, 0.f};

    uint4 kpre[4];
    uint2 vpa[4], vpb[4];
#pragma unroll
    for (int j = 0; j < 4; j++) {
        int e = tid + j * 256;
        { int tok = e >> 3, g = e & 7;
          kpre[j] = *(const uint4*)(kg + (long)tok * DHD + 8 * g); }
        { int kpt = e >> 4, d4 = (e & 15) << 2;
          vpa[j] = *(const uint2*)(vg + (long)(2 * kpt) * DHD + d4);
          vpb[j] = *(const uint2*)(vg + (long)(2 * kpt + 1) * DHD + d4); }
    }

    for (int ch = 0; ch < NCH2; ch++) {
        __syncthreads();
#pragma unroll
        for (int j = 0; j < 4; j++) {
            int e = tid + j * 256;
            { int tok = e >> 3, g = e & 7;
              *(uint4*)&Ks[tok * 32 + 4 * (g ^ (tok & 7))] = kpre[j]; }
            { int kpt = e >> 4, d4 = (e & 15) << 2;
              uint4 w;
              w.x = prmtb(vpa[j].x, vpb[j].x, 0x5410);
              w.y = prmtb(vpa[j].x, vpb[j].x, 0x7632);
              w.z = prmtb(vpa[j].y, vpb[j].y, 0x5410);
              w.w = prmtb(vpa[j].y, vpb[j].y, 0x7632);
              *(uint4*)&Vs[kpt * 64 + (d4 ^ ((kpt & 3) << 3))] = w; }
        }
        if (ch + 1 < NCH2) {
            const __half* kc = kg + (long)(ch + 1) * SN2 * DHD;
            const __half* vc = vg + (long)(ch + 1) * SN2 * DHD;
#pragma unroll
            for (int j = 0; j < 4; j++) {
                int e = tid + j * 256;
                { int tok = e >> 3, g = e & 7;
                  kpre[j] = *(const uint4*)(kc + (long)tok * DHD + 8 * g); }
                { int kpt = e >> 4, d4 = (e & 15) << 2;
                  vpa[j] = *(const uint2*)(vc + (long)(2 * kpt) * DHD + d4);
                  vpb[j] = *(const uint2*)(vc + (long)(2 * kpt + 1) * DHD + d4); }
            }
        }
        __syncthreads();

        float sacc[4][4];
#pragma unroll
        for (int nt = 0; nt < 4; nt++)
#pragma unroll
            for (int i = 0; i < 4; i++) sacc[nt][i] = 0.f;
#pragma unroll
        for (int s = 0; s < 4; s++) {
            uint32_t bf[4][2];
#pragma unroll
            for (int nt = 0; nt < 4; nt++) {
                int c = warpn * 32 + nt * 8 + lg;
                bf[nt][0] = Ks[c * 32 + lt + 4 * ((2 * s) ^ (c & 7))];
                bf[nt][1] = Ks[c * 32 + lt + 4 * ((2 * s + 1) ^ (c & 7))];
            }
#pragma unroll
            for (int nt = 0; nt < 4; nt++)
                mma_f16(sacc[nt], aq[s], bf[nt]);
        }

#pragma unroll
        for (int half_ = 0; half_ < 2; half_++) {
            float mx = -1e30f;
#pragma unroll
            for (int nt = 0; nt < 4; nt++) {
                mx = fmaxf(mx, sacc[nt][half_ * 2]);
                mx = fmaxf(mx, sacc[nt][half_ * 2 + 1]);
            }
            mx = fmaxf(mx, __shfl_xor_sync(~0u, mx, 1));
            mx = fmaxf(mx, __shfl_xor_sync(~0u, mx, 2));
            if (lt == 0) redm[(warpm * 16 + half_ * 8 + lg) * 4 + warpn] = mx;
        }
        __syncthreads();

        float scale[2];
#pragma unroll
        for (int half_ = 0; half_ < 2; half_++) {
            int row = warpm * 16 + half_ * 8 + lg;
            float mch = fmaxf(fmaxf(redm[row * 4 + 0], redm[row * 4 + 1]),
                              fmaxf(redm[row * 4 + 2], redm[row * 4 + 3]));
            float mnew = fmaxf(mprev[half_], mch);
            scale[half_] = __expf(mprev[half_] - mnew);
            mprev[half_] = mnew;
            float s = 0.f;
#pragma unroll
            for (int nt = 0; nt < 4; nt++) {
                float e0 = __expf(sacc[nt][half_ * 2]     - mnew);
                float e1 = __expf(sacc[nt][half_ * 2 + 1] - mnew);
                sacc[nt][half_ * 2]     = e0;
                sacc[nt][half_ * 2 + 1] = e1;
                s += e0 + e1;
            }
            s += __shfl_xor_sync(~0u, s, 1);
            s += __shfl_xor_sync(~0u, s, 2);
            if (lt == 0) reds[row * 4 + warpn] = s;
#pragma unroll
            for (int nt = 0; nt < 4; nt++) {
                int kp = warpn * 16 + nt * 4 + lt;
                Ps[row * 64 + (kp ^ ((row & 7) << 2))] =
                    h2pack(sacc[nt][half_ * 2], sacc[nt][half_ * 2 + 1]);
            }
        }
        __syncthreads();

#pragma unroll
        for (int half_ = 0; half_ < 2; half_++) {
            int row = warpm * 16 + half_ * 8 + lg;
            lsum[half_] = lsum[half_] * scale[half_]
                        + reds[row * 4 + 0] + reds[row * 4 + 1]
                        + reds[row * 4 + 2] + reds[row * 4 + 3];
        }
#pragma unroll
        for (int nt = 0; nt < 2; nt++) {
            oacc[nt][0] *= scale[0]; oacc[nt][1] *= scale[0];
            oacc[nt][2] *= scale[1]; oacc[nt][3] *= scale[1];
        }

#pragma unroll
        for (int s = 0; s < 8; s++) {
            const int kp0 = s * 8;
            int mr = warpm * 16 + lg;
            uint32_t af[4];
            af[0] = Ps[mr * 64 + ((kp0 + lt) ^ ((mr & 7) << 2))];
            af[1] = Ps[(mr + 8) * 64 + ((kp0 + lt) ^ (((mr + 8) & 7) << 2))];
            af[2] = Ps[mr * 64 + ((kp0 + lt + 4) ^ ((mr & 7) << 2))];
            af[3] = Ps[(mr + 8) * 64 + ((kp0 + lt + 4) ^ (((mr + 8) & 7) << 2))];
            uint32_t bf[2][2];
#pragma unroll
            for (int nt = 0; nt < 2; nt++) {
                int d = warpn * 16 + nt * 8 + lg;
                bf[nt][0] = Vs[(kp0 + lt) * 64 + (d ^ (lt << 3))];
                bf[nt][1] = Vs[(kp0 + lt + 4) * 64 + (d ^ (lt << 3))];
            }
#pragma unroll
            for (int nt = 0; nt < 2; nt++)
                mma_f16(oacc[nt], af, bf[nt]);
        }
    }

    __half* outb = h_a3vT + (long)bh * DHD * MM;
#pragma unroll
    for (int half_ = 0; half_ < 2; half_++) {
        float inv = 1.f / lsum[half_];
        int r = m0 + warpm * 16 + half_ * 8 + lg;
#pragma unroll
        for (int nt = 0; nt < 2; nt++) {
            int d = warpn * 16 + nt * 8 + 2 * lt;
            outb[(long)d * MM + r]       = __float2half(oacc[nt][half_ * 2] * inv);
            outb[(long)(d + 1) * MM + r] = __float2half(oacc[nt][half_ * 2 + 1] * inv);
        }
    }
}

// ---------------- fused LayerNorm + weight conversion + colmax reset -----------
__global__ __launch_bounds__(256) void prep_kernel(
    const float* __restrict__ x, const float* __restrict__ w, const float* __restrict__ b,
    const float* __restrict__ wq, const float* __restrict__ wo)
{
    if (blockIdx.x == 0 && threadIdx.x == 0) g_colmax = 0.f;
    if (blockIdx.x < BB * NN) {
        long row = blockIdx.x;
        const float* xr = x + row * DD;
        int t = threadIdx.x;
        float v0 = xr[t], v1 = xr[t + 256];
        __shared__ float red[32];

        float s = v0 + v1;
        for (int o = 16; o > 0; o >>= 1) s += __shfl_xor_sync(~0u, s, o);
        if ((t & 31) == 0) red[t >> 5] = s;
        __syncthreads();
        if (t < 32) {
            float ss = (t < 8) ? red[t] : 0.f;
            for (int o = 4; o > 0; o >>= 1) ss += __shfl_xor_sync(~0u, ss, o);
            if (t == 0) red[0] = ss;
        }
        __syncthreads();
        float mu = red[0] * (1.f / DD);
        __syncthreads();

        float d0 = v0 - mu, d1 = v1 - mu;
        float q = d0 * d0 + d1 * d1;
        for (int o = 16; o > 0; o >>= 1) q += __shfl_xor_sync(~0u, q, o);
        if ((t & 31) == 0) red[t >> 5] = q;
        __syncthreads();
        if (t < 32) {
            float ss = (t < 8) ? red[t] : 0.f;
            for (int o = 4; o > 0; o >>= 1) ss += __shfl_xor_sync(~0u, ss, o);
            if (t == 0) red[0] = ss;
        }
        __syncthreads();
        float inv = rsqrtf(red[0] * (1.f / DD) + 1e-5f);
        h_xn[row * DD + t]       = __float2half(d0 * inv * w[t]       + b[t]);
        h_xn[row * DD + t + 256] = __float2half(d1 * inv * w[t + 256] + b[t + 256]);
    } else {
        int i = (blockIdx.x - BB * NN) * 256 + threadIdx.x;
        {
            int n = i / DD, k2 = i % DD;
            h_wqkvT[i] = __float2half(wq[(long)k2 * (3 * DD) + n]);
        }
        if (i < DD * DD) {
            int n = i / DD, k2 = i % DD;
            h_woutT[i] = __float2half(wo[(long)k2 * DD + n]);
        }
    }
}

// ---------------- landmarks ----------------------------------------------------
__global__ void landmarks()
{
    long i = (long)blockIdx.x * 256 + threadIdx.x;
    int dp = i & 31; long r = i >> 5;
    int m = r % MM;  int bh = r / MM;
    long base = ((long)bh * NN + m * LLm) * DHD + dp * 2;
    float sq0 = 0.f, sq1 = 0.f, sk0 = 0.f, sk1 = 0.f;
#pragma unroll
    for (int u = 0; u < LLm; u++) {
        float2 fq = __half22float2(*(const __half2*)(h_q + base + u * DHD));
        float2 fk = __half22float2(*(const __half2*)(h_k + base + u * DHD));
        sq0 += fq.x; sq1 += fq.y;
        sk0 += fk.x; sk1 += fk.y;
    }
    long out = ((long)bh * MM + m) * DHD + dp * 2;
    *(uint32_t*)(h_ql + out) = h2pack(sq0 * (1.f / LLm), sq1 * (1.f / LLm));
    *(uint32_t*)(h_kl + out) = h2pack(sk0 * (1.f / LLm), sk1 * (1.f / LLm));
}

// ---------------- pinv colmax + zinit -------------------------------------------
__global__ __launch_bounds__(256) void colmax_kernel()
{
    int bh = blockIdx.x, j = threadIdx.x;
    const __half* a = h_a2 + (long)bh * MM * MM;
    float s = 0.f;
    for (int i = 0; i < MM; i++) s += __half2float(a[i * MM + j]);
    __shared__ float red[32];
    float m = s;
    for (int o = 16; o > 0; o >>= 1) m = fmaxf(m, __shfl_xor_sync(~0u, m, o));
    if ((j & 31) == 0) red[j >> 5] = m;
    __syncthreads();
    if (j < 32) {
        float m2 = (j < 8) ? red[j] : -1e30f;
        for (int o = 4; o > 0; o >>= 1) m2 = fmaxf(m2, __shfl_xor_sync(~0u, m2, o));
        if (j == 0) atomicMax((int*)&g_colmax, __float_as_int(m2));
    }
}

__global__ void zinit()
{
    long i = (long)blockIdx.x * 256 + threadIdx.x;
    int col = i % MM; long r = i / MM;
    int row = r % MM; int bh = r / MM;
    float inv = 1.f / g_colmax;
    h_zT[i] = __float2half(__half2float(h_a2[i]) * inv);
    h_z [i] = __float2half(__half2float(h_a2[((long)bh * MM + col) * MM + row]) * inv);
}

// =============================================================================
// att_conv: smem sliding-window depthwise conv + reshape (proven form).
// =============================================================================
__global__ __launch_bounds__(256, 2) void att_conv(const float* __restrict__ rw)
{
    __shared__ uint32_t Vt[32 * 161];
    __shared__ float ws[KC];

    const int bh = blockIdx.x >> 5;
    const int n0 = (blockIdx.x & 31) * 128;
    const int b = bh / HH, h = bh % HH;
    const int tid = threadIdx.x;

    const __half* vb = h_v + (long)bh * NN * DHD;

#pragma unroll
    for (int k = 0; k < 20; k++) {
        int i = tid + k * 256;
        int tl = i >> 5, dp = i & 31;
        int tok = n0 - 16 + tl;
        uint32_t val = 0;
        if (tok >= 0 && tok < NN)
            val = *(const uint32_t*)(vb + (long)tok * DHD + dp * 2);
        Vt[dp * 161 + tl] = val;
    }
    if (tid < KC) ws[tid] = rw[h * KC + tid];
    __syncthreads();

    const int tg = tid >> 5, dp = tid & 31;
    const int nl0 = tg * 16;

    float acc[32];
    const __half* ob = h_o + (long)bh * NN * DHD;
#pragma unroll
    for (int t = 0; t < 16; t++) {
        uint32_t ov = *(const uint32_t*)(ob + (long)(n0 + nl0 + t) * DHD + dp * 2);
        float2 f = __half22float2(*(const __half2*)&ov);
        acc[2 * t] = f.x; acc[2 * t + 1] = f.y;
    }
#pragma unroll
    for (int s = 0; s < 48; s++) {
        float2 v2 = __half22float2(*(const __half2*)&Vt[dp * 161 + nl0 + s]);
        const int tlo = (s - 32 > 0) ? s - 32 : 0;
        const int thi = (s < 15) ? s : 15;
#pragma unroll
        for (int t = tlo; t <= thi; t++) {
            float w = ws[s - t];
            acc[2 * t]     += w * v2.x;
            acc[2 * t + 1] += w * v2.y;
        }
    }
    __half* attb = h_att + ((long)(b * NN + n0 + nl0)) * DD + h * DHD + dp * 2;
#pragma unroll
    for (int t = 0; t < 16; t++) {
        *(uint32_t*)(attb + (long)t * DD) = h2pack(acc[2 * t], acc[2 * t + 1]);
    }
}

// ---------------- host orchestration -------------------------------------------
extern "C" void kernel_launch(void* const* d_in, const int* in_sizes, int n_in,
                              void* d_out, int out_size)
{
    const float* x      = (const float*)d_in[0];
    const float* norm_w = (const float*)d_in[1];
    const float* norm_b = (const float*)d_in[2];
    const float* w_qkv  = (const float*)d_in[3];
    const float* w_out  = (const float*)d_in[4];
    const float* b_out  = (const float*)d_in[5];
    const float* res_w  = (const float*)d_in[6];
    float* y = (float*)d_out;

    __half *p_xn, *p_wqkvT, *p_woutT, *p_q, *p_k, *p_v, *p_ql, *p_kl;
    __half *p_a2, *p_z, *p_zT, *p_z2, *p_z2T, *p_xz, *p_t1T, *p_t2T, *p_a3vT, *p_WT, *p_att;
    cudaGetSymbolAddress((void**)&p_xn,   h_xn);
    cudaGetSymbolAddress((void**)&p_wqkvT,h_wqkvT);
    cudaGetSymbolAddress((void**)&p_woutT,h_woutT);
    cudaGetSymbolAddress((void**)&p_q,    h_q);
    cudaGetSymbolAddress((void**)&p_k,    h_k);
    cudaGetSymbolAddress((void**)&p_v,    h_v);
    cudaGetSymbolAddress((void**)&p_ql,   h_ql);
    cudaGetSymbolAddress((void**)&p_kl,   h_kl);
    cudaGetSymbolAddress((void**)&p_a2,   h_a2);
    cudaGetSymbolAddress((void**)&p_z,    h_z);
    cudaGetSymbolAddress((void**)&p_zT,   h_zT);
    cudaGetSymbolAddress((void**)&p_z2,   h_z2);
    cudaGetSymbolAddress((void**)&p_z2T,  h_z2T);
    cudaGetSymbolAddress((void**)&p_xz,   h_xz);
    cudaGetSymbolAddress((void**)&p_t1T,  h_t1T);
    cudaGetSymbolAddress((void**)&p_t2T,  h_t2T);
    cudaGetSymbolAddress((void**)&p_a3vT, h_a3vT);
    cudaGetSymbolAddress((void**)&p_WT,   h_WT);
    cudaGetSymbolAddress((void**)&p_att,  h_att);

    const long MM2 = (long)MM * MM;
    void* nul = nullptr;

    // 1. LayerNorm + weight conversion + colmax reset
    prep_kernel<<<BB * NN + (3 * DD * DD) / 256, 256>>>(
        x, norm_w, norm_b, w_qkv, w_out);
    // 2. qkv GEMM with fused split
    gemm_h<128, 1><<<dim3((3 * DD) / 128, (BB * NN) / 128, 1), 256>>>(
        p_xn, p_wqkvT, p_q, p_k, p_v,
        BB * NN, 3 * DD, DD, 0, 0, 0, 1.f, 0.f);
    // 3. landmarks
    landmarks<<<(BH * MM * 32) / 256, 256>>>();
    // 4. a2 = softmax(ql @ kl^T)
    sim_softmax_h<<<dim3(MM / 64, 1, BH), 256>>>(
        p_ql, p_kl, p_a2, (long)MM * DHD, (long)MM * DHD, MM2);
    // 5. pinv init
    colmax_kernel<<<BH, 256>>>();
    zinit<<<(int)((long)BH * MM * MM / 256), 256>>>();
    // 6. Newton-Schulz
    __half *zin = p_z, *zinT = p_zT, *zout = p_z2, *zoutT = p_z2T;
    for (int it = 0; it < NITER; it++) {
        gemm_h<64, 3><<<dim3(MM / 64, MM / 128, BH), 256>>>(
            p_a2, zinT, p_xz, nul, p_t1T, MM, MM, MM, MM2, MM2, MM2, 1.f, 7.f);
        gemm_h<64, 3><<<dim3(MM / 64, MM / 128, BH), 256>>>(
            p_xz, p_t1T, nul, nul, p_t2T, MM, MM, MM, MM2, MM2, MM2, 1.f, 15.f);
        gemm_h<64, 3><<<dim3(MM / 64, MM / 128, BH), 256>>>(
            p_xz, p_t2T, nul, nul, p_t1T, MM, MM, MM, MM2, MM2, MM2, 1.f, 13.f);
        gemm_h<64, 3><<<dim3(MM / 64, MM / 128, BH), 256>>>(
            zin, p_t1T, zout, zoutT, nul, MM, MM, MM, MM2, MM2, MM2, 0.25f, 0.f);
        __half* t;
        t = zin;  zin  = zout;  zout  = t;
        t = zinT; zinT = zoutT; zoutT = t;
    }
    // 7. a3vT = (softmax(ql @ k^T) @ v)^T  (flash)
    a3v_flash_h<<<dim3(MM / 32, 1, BH), 256>>>();
    // 8. WT = (z @ a3v)^T
    gemm_h<64, 3><<<dim3(1, MM / 128, BH), 256>>>(
        zin, p_a3vT, nul, p_WT, nul, MM, DHD, MM,
        MM2, (long)DHD * MM, (long)DHD * MM, 1.f, 0.f);
    // 9. o = softmax(q @ kl^T) @ W  (fully fused)
    sim_out_h<<<dim3(NN / 64, 1, BH), 256>>>();
    // 10. att = reshape(o) + conv(v)
    att_conv<<<BH * (NN / 128), 256>>>(res_w);
    // 11. y = att @ w_out + x + b_out
    gemm_h<128, 2><<<dim3(DD / 128, (BB * NN) / 128, 1), 256>>>(
        p_att, p_woutT, y, (void*)x, (void*)b_out,
        BB * NN, DD, DD, 0, 0, 0, 1.f, 0.f);
}